// round 11
// baseline (speedup 1.0000x reference)
#include <cuda_runtime.h>
#include <cstdint>

#define B_  4
#define T_  4096
#define TKP 1024
#define DM  1024
#define HD  128
#define SCALE_INV 0.08838834764831845f   // 1/sqrt(128)

// ---------------- static device scratch ----------------
__device__ float  g_xp[B_ * TKP * DM];   // pooled x: tf32-rounded, DM k-interleaved per 8-block
__device__ float  g_Q [B_ * T_  * HD];   // d-dim interleaved [0,4,1,5,2,6,3,7] per 8-block
__device__ float  g_K [B_ * TKP * HD];   // d-dim interleaved
__device__ float  g_V [B_ * TKP * HD];   // normal layout (proj output, tf32-rounded)
__device__ float  g_Vt[B_ * TKP * HD];   // transposed [b][d][key], key-interleaved per 8-block
__device__ float  g_Wt[3 * DM * HD];     // tf32 weights, layout [which][kblk][n][8 interleaved]
__device__ float  g_cos[T_ * 64];
__device__ float  g_sin[T_ * 64];
__device__ double g_theta[64];

// ---------------- helpers ----------------
__device__ __forceinline__ unsigned f2t(float x) {
    unsigned r; asm("cvt.rna.tf32.f32 %0, %1;" : "=r"(r) : "f"(x)); return r;
}
__device__ __forceinline__ float f2tf(float x) { return __uint_as_float(f2t(x)); }
__device__ __forceinline__ float4 f2tf4(float4 v) {
    return make_float4(f2tf(v.x), f2tf(v.y), f2tf(v.z), f2tf(v.w));
}
__device__ __forceinline__ void mma8(float* d,
                                     float a0, float a1, float a2, float a3,
                                     float b0, float b1) {
    asm volatile("mma.sync.aligned.m16n8k8.row.col.f32.tf32.tf32.f32 "
                 "{%0,%1,%2,%3},{%4,%5,%6,%7},{%8,%9},{%0,%1,%2,%3};"
                 : "+f"(d[0]), "+f"(d[1]), "+f"(d[2]), "+f"(d[3])
                 : "r"(__float_as_uint(a0)), "r"(__float_as_uint(a1)),
                   "r"(__float_as_uint(a2)), "r"(__float_as_uint(a3)),
                   "r"(__float_as_uint(b0)), "r"(__float_as_uint(b1)));
}
__device__ __forceinline__ void cpa16(uint32_t dst, const void* src) {
    asm volatile("cp.async.cg.shared.global [%0], [%1], 16;" :: "r"(dst), "l"(src));
}

// ---------------- RoPE tables (R6-R8 proven pair) ----------------
__global__ void theta_k() {
    int i = threadIdx.x;
    g_theta[i] = exp(((double)(-i) / 64.0) * log(10000.0));
}
__global__ void rope_table_k() {
    int t = blockIdx.x, i = threadIdx.x;
    float thf = (float)g_theta[i];
    float arg = (float)t * thf;          // fp32 product, matching reference
    const double TWO_PI  = 6.283185307179586476925286766559;
    const double INV2PI  = 0.15915494309189533576888376337251;
    double da = (double)arg;
    double k  = rint(da * INV2PI);
    float  r  = (float)(da - k * TWO_PI);
    g_cos[t * 64 + i] = cosf(r);
    g_sin[t * 64 + i] = sinf(r);
}

// ---------------- weights -> tf32, layout [which][kblk][n][8 interleaved] ----------------
__global__ void cvtW_k(const float* __restrict__ Wq, const float* __restrict__ Wk,
                       const float* __restrict__ Wv) {
    int g = blockIdx.x * 256 + threadIdx.x;   // 3*128*128 = 49152 threads
    int n = g & 127;
    int kb = (g >> 7) & 127;
    int which = g >> 14;
    const float* W = (which == 0) ? Wq : (which == 1 ? Wk : Wv);
    float w[8];
#pragma unroll
    for (int j = 0; j < 8; j++) w[j] = f2tf(W[(size_t)(kb * 8 + j) * HD + n]);
    float* dst = g_Wt + (((size_t)which * 128 + kb) * 128 + n) * 8;
    *(float4*)(dst)     = make_float4(w[0], w[4], w[1], w[5]);
    *(float4*)(dst + 4) = make_float4(w[2], w[6], w[3], w[7]);
}

// ---------------- stride-4 mean pool: tf32-round + k-interleave the DM dim ----------------
__global__ void pool_x_k(const float* __restrict__ x) {
    int g  = blockIdx.x * 256 + threadIdx.x;     // B*TKP*128 threads, one 8-block each
    int d8 = g & 127;
    int row = g >> 7;                            // b*1024 + tp
    int b   = row >> 10, tp = row & 1023;
    const float* base = x + ((size_t)b * T_ + 4 * tp) * DM + d8 * 8;
    float v[8] = {0.f, 0.f, 0.f, 0.f, 0.f, 0.f, 0.f, 0.f};
#pragma unroll
    for (int r = 0; r < 4; r++) {
        float4 a = *(const float4*)(base + (size_t)r * DM);
        float4 c = *(const float4*)(base + (size_t)r * DM + 4);
        v[0] += a.x; v[1] += a.y; v[2] += a.z; v[3] += a.w;
        v[4] += c.x; v[5] += c.y; v[6] += c.z; v[7] += c.w;
    }
#pragma unroll
    for (int j = 0; j < 8; j++) v[j] = f2tf(v[j] * 0.25f);
    float* dst = g_xp + (size_t)row * DM + d8 * 8;
    *(float4*)(dst)     = make_float4(v[0], v[4], v[1], v[5]);
    *(float4*)(dst + 4) = make_float4(v[2], v[6], v[3], v[7]);
}

// ---------------- projection GEMM: interleaved A (K/V) and B, cp.async DB ----
#define AST 36
#define ABUF (128 * AST)
#define BBUF 4096                         // 4 kblk x 128 n x 8
__global__ void __launch_bounds__(256, 2) proj_k(const float* __restrict__ x) {
    extern __shared__ __align__(16) float psm[];
    float* As = psm;
    float* Bs = psm + 2 * ABUF;

    int bid = blockIdx.x;
    const float* A; const float* Wm; float* Cm; int m0;
    bool isQ = false, roundV = false;
    if (bid < 128)      { A = x;    Wm = g_Wt;                Cm = g_Q; m0 = bid * 128; isQ = true; }
    else if (bid < 160) { A = g_xp; Wm = g_Wt + DM * HD;      Cm = g_K; m0 = (bid - 128) * 128; }
    else                { A = g_xp; Wm = g_Wt + 2 * DM * HD;  Cm = g_V; m0 = (bid - 160) * 128; roundV = true; }

    int tid  = threadIdx.x;
    int lane = tid & 31, wid = tid >> 5;
    int gid  = lane >> 2, tig = lane & 3;
    int wm = wid >> 1, wn = wid & 1;

    uint32_t sA = (uint32_t)__cvta_generic_to_shared(As);
    uint32_t sB = (uint32_t)__cvta_generic_to_shared(Bs);
    int ar = tid >> 3, ac = tid & 7;

    auto stage = [&](int kb, int buf) {
#pragma unroll
        for (int it = 0; it < 4; it++) {
            int r = ar + it * 32;
            cpa16(sA + (uint32_t)((buf * ABUF + r * AST + ac * 4) * 4),
                  A + (size_t)(m0 + r) * DM + kb * 32 + ac * 4);
        }
#pragma unroll
        for (int it = 0; it < 4; it++) {
            int idx = it * 256 + tid;
            cpa16(sB + (uint32_t)((buf * BBUF + idx * 4) * 4),
                  Wm + (size_t)kb * 4096 + idx * 4);
        }
        asm volatile("cp.async.commit_group;");
    };

    float C[2][8][4];
#pragma unroll
    for (int mf = 0; mf < 2; mf++)
#pragma unroll
        for (int nf = 0; nf < 8; nf++)
#pragma unroll
            for (int j = 0; j < 4; j++) C[mf][nf][j] = 0.f;

    stage(0, 0);
    stage(1, 1);

    for (int kb = 0; kb < 32; kb++) {
        if (kb < 30) { asm volatile("cp.async.wait_group 1;"); }
        else         { asm volatile("cp.async.wait_group 0;"); }
        __syncthreads();
        const float* Ab = As + (kb & 1) * ABUF;
        const float* Bb = Bs + (kb & 1) * BBUF;
#pragma unroll
        for (int ks = 0; ks < 4; ks++) {
            int k0 = ks * 8;
            float ah[2][4];
            if (isQ) {
#pragma unroll
                for (int mf = 0; mf < 2; mf++) {
                    int mb = wm * 32 + mf * 16;
                    ah[mf][0] = f2tf(Ab[(mb + gid)     * AST + k0 + tig]);
                    ah[mf][1] = f2tf(Ab[(mb + gid + 8) * AST + k0 + tig]);
                    ah[mf][2] = f2tf(Ab[(mb + gid)     * AST + k0 + tig + 4]);
                    ah[mf][3] = f2tf(Ab[(mb + gid + 8) * AST + k0 + tig + 4]);
                }
            } else {
#pragma unroll
                for (int mf = 0; mf < 2; mf++) {
                    int mb = wm * 32 + mf * 16;
                    float2 a0 = *(const float2*)(Ab + (mb + gid)     * AST + k0 + 2 * tig);
                    float2 a1 = *(const float2*)(Ab + (mb + gid + 8) * AST + k0 + 2 * tig);
                    ah[mf][0] = a0.x; ah[mf][1] = a1.x; ah[mf][2] = a0.y; ah[mf][3] = a1.y;
                }
            }
#pragma unroll
            for (int nf = 0; nf < 8; nf++) {
                int nb = wn * 64 + nf * 8 + gid;
                float2 bb = *(const float2*)(Bb + (ks * 128 + nb) * 8 + 2 * tig);
#pragma unroll
                for (int mf = 0; mf < 2; mf++)
                    mma8(C[mf][nf], ah[mf][0], ah[mf][1], ah[mf][2], ah[mf][3], bb.x, bb.y);
            }
        }
        __syncthreads();
        if (kb + 2 < 32) stage(kb + 2, kb & 1);
    }

#pragma unroll
    for (int mf = 0; mf < 2; mf++) {
        int r0 = m0 + wm * 32 + mf * 16 + gid;
#pragma unroll
        for (int nf = 0; nf < 8; nf++) {
            int col = wn * 64 + nf * 8 + 2 * tig;
            float v0 = C[mf][nf][0], v1 = C[mf][nf][1];
            float v2 = C[mf][nf][2], v3 = C[mf][nf][3];
            if (roundV) { v0 = f2tf(v0); v1 = f2tf(v1); v2 = f2tf(v2); v3 = f2tf(v3); }
            *(float2*)(Cm + (size_t)r0 * HD + col)       = make_float2(v0, v1);
            *(float2*)(Cm + (size_t)(r0 + 8) * HD + col) = make_float2(v2, v3);
        }
    }
}

// ---------------- RoPE + tf32-round + d-interleave, in place (Q, K) ----------------
__global__ void ropep_k(int which) {
    float* X   = which ? g_K : g_Q;
    int mask   = which ? (TKP - 1) : (T_ - 1);
    float scl  = which ? 1.f : SCALE_INV;
    int g  = blockIdx.x * 256 + threadIdx.x;
    int b8 = g & 7;
    int row = g >> 3;
    int pos = row & mask;
    const float4* cp = (const float4*)(g_cos + pos * 64 + b8 * 8);
    const float4* sp = (const float4*)(g_sin + pos * 64 + b8 * 8);
    float c[8], s[8], x1[8], x2[8];
    *(float4*)(c)     = cp[0]; *(float4*)(c + 4) = cp[1];
    *(float4*)(s)     = sp[0]; *(float4*)(s + 4) = sp[1];
    float* p = X + (size_t)row * HD + b8 * 8;
    *(float4*)(x1)     = *(float4*)(p);      *(float4*)(x1 + 4) = *(float4*)(p + 4);
    *(float4*)(x2)     = *(float4*)(p + 64); *(float4*)(x2 + 4) = *(float4*)(p + 68);
    float o1[8], o2[8];
#pragma unroll
    for (int j = 0; j < 8; j++) {
        o1[j] = (x1[j] * c[j] - x2[j] * s[j]) * scl;
        o2[j] = (x2[j] * c[j] + x1[j] * s[j]) * scl;
    }
    *(float4*)(p)      = f2tf4(make_float4(o1[0], o1[4], o1[1], o1[5]));
    *(float4*)(p + 4)  = f2tf4(make_float4(o1[2], o1[6], o1[3], o1[7]));
    *(float4*)(p + 64) = f2tf4(make_float4(o2[0], o2[4], o2[1], o2[5]));
    *(float4*)(p + 68) = f2tf4(make_float4(o2[2], o2[6], o2[3], o2[7]));
}

// ---------------- zero output ----------------
__global__ void zero_k(float* __restrict__ out) {
    ((float4*)out)[blockIdx.x * 256 + threadIdx.x] = make_float4(0.f, 0.f, 0.f, 0.f);
}

// ---------------- V transpose: [b][key][d] -> [b][d][key-interleaved] ----------------
#define VTST 132
__global__ void vtr_k() {
    __shared__ __align__(16) float ts[64 * VTST];
    int bb = blockIdx.x >> 4;
    int k0 = (blockIdx.x & 15) * 64;
    int tid = threadIdx.x;
    const float* src = g_V + ((size_t)bb * TKP + k0) * HD;
#pragma unroll
    for (int it = 0; it < 8; it++) {
        int f = it * 256 + tid;          // 2048 float4s = 64 keys x 32 f4
        int ky = f >> 5, c4 = f & 31;
        *(float4*)(ts + ky * VTST + c4 * 4) = *(const float4*)(src + (size_t)ky * HD + c4 * 4);
    }
    __syncthreads();
    int d = tid >> 1, h = tid & 1;       // 128 d-rows x 2 key-halves
    float* dst = g_Vt + ((size_t)bb * HD + d) * TKP + k0 + h * 32;
#pragma unroll
    for (int q8 = 0; q8 < 4; q8++) {
        int kb = h * 32 + q8 * 8;
        float4 v0 = make_float4(ts[(kb + 0) * VTST + d], ts[(kb + 4) * VTST + d],
                                ts[(kb + 1) * VTST + d], ts[(kb + 5) * VTST + d]);
        float4 v1 = make_float4(ts[(kb + 2) * VTST + d], ts[(kb + 6) * VTST + d],
                                ts[(kb + 3) * VTST + d], ts[(kb + 7) * VTST + d]);
        *(float4*)(dst + q8 * 8)     = v0;
        *(float4*)(dst + q8 * 8 + 4) = v1;
    }
}

// ---------------- flash attention: LDS.64 frags everywhere in mma loops ----------
#define QST 136
#define KST 136
#define VST 72
#define PST 68
__global__ void __launch_bounds__(256, 2) attn_k(const float* __restrict__ alpha_p,
                                                 float* __restrict__ Out)
{
    extern __shared__ __align__(16) float sm[];
    float* Qs  = sm;                        // 64 x 136
    float* KVs = Qs + 64 * QST;             // K: 64 x 136 / V: 128 x 72 (9216 floats)
    float* Ps  = KVs + 9216;                // 64 x 68
    float* wmx = Ps + 64 * PST;             // [2][64]
    float* wsp = wmx + 128;
    float* wsx = wsp + 128;

    int tid  = threadIdx.x;
    int lane = tid & 31, wid = tid >> 5;
    int gid  = lane >> 2, tig = lane & 3;
    int rg   = wid >> 1, half = wid & 1;
    int Q0 = blockIdx.x * 64;
    int b  = blockIdx.y;
    const float* Qb = g_Q + ((size_t)b * T_ + Q0) * HD;
    const float* Kb = g_K + (size_t)b * TKP * HD;
    const float* Vb = g_Vt + (size_t)b * HD * TKP;

    uint32_t sQ  = (uint32_t)__cvta_generic_to_shared(Qs);
    uint32_t sKV = (uint32_t)__cvta_generic_to_shared(KVs);
    int sr = tid >> 3, sc = tid & 7;

#pragma unroll
    for (int it = 0; it < 2; it++) {
        int r = sr + it * 32;
        cpa16(sQ + (uint32_t)((r * QST + sc * 4) * 4),      Qb + (size_t)r * HD + sc * 4);
        cpa16(sQ + (uint32_t)((r * QST + 32 + sc * 4) * 4), Qb + (size_t)r * HD + 32 + sc * 4);
        cpa16(sQ + (uint32_t)((r * QST + 64 + sc * 4) * 4), Qb + (size_t)r * HD + 64 + sc * 4);
        cpa16(sQ + (uint32_t)((r * QST + 96 + sc * 4) * 4), Qb + (size_t)r * HD + 96 + sc * 4);
    }
    asm volatile("cp.async.commit_group;");

    int r0 = rg * 16 + gid, r1 = r0 + 8;
    int kmax0 = (Q0 + r0) >> 2, kmax1 = (Q0 + r1) >> 2;
    int bt = Q0 >> 8;
    int n0 = half * 32;
    int cc = half * 64;

    float m0r = -1e30f, m1r = -1e30f;
    float sp0 = 0.f, sp1 = 0.f, sx0 = 0.f, sx1 = 0.f;
    float Om[8][4], Ox[8][4];
#pragma unroll
    for (int nf = 0; nf < 8; nf++)
#pragma unroll
        for (int j = 0; j < 4; j++) { Om[nf][j] = 0.f; Ox[nf][j] = 0.f; }

    for (int kt = 0; kt < 16; kt++) {
        __syncthreads();                                    // (A)
#pragma unroll
        for (int it = 0; it < 2; it++) {
            int r = sr + it * 32;
            const float* src = Kb + (size_t)(kt * 64 + r) * HD;
            cpa16(sKV + (uint32_t)((r * KST + sc * 4) * 4),      src + sc * 4);
            cpa16(sKV + (uint32_t)((r * KST + 32 + sc * 4) * 4), src + 32 + sc * 4);
            cpa16(sKV + (uint32_t)((r * KST + 64 + sc * 4) * 4), src + 64 + sc * 4);
            cpa16(sKV + (uint32_t)((r * KST + 96 + sc * 4) * 4), src + 96 + sc * 4);
        }
        asm volatile("cp.async.commit_group;");
        asm volatile("cp.async.wait_group 0;");
        __syncthreads();                                    // (B)

        // S = Q K^T — LDS.64 frags
        float c[4][4];
#pragma unroll
        for (int nf = 0; nf < 4; nf++)
#pragma unroll
            for (int j = 0; j < 4; j++) c[nf][j] = 0.f;
#pragma unroll
        for (int ks = 0; ks < 16; ks++) {
            int k0 = ks * 8;
            float2 qa0 = *(const float2*)(Qs + r0 * QST + k0 + 2 * tig);
            float2 qa1 = *(const float2*)(Qs + r1 * QST + k0 + 2 * tig);
#pragma unroll
            for (int nf = 0; nf < 4; nf++) {
                float2 kb2 = *(const float2*)(KVs + (n0 + nf * 8 + gid) * KST + k0 + 2 * tig);
                mma8(c[nf], qa0.x, qa1.x, qa0.y, qa1.y, kb2.x, kb2.y);
            }
        }
        float t0 = -1e30f, t1 = -1e30f;
#pragma unroll
        for (int nf = 0; nf < 4; nf++) {
            t0 = fmaxf(t0, fmaxf(c[nf][0], c[nf][1]));
            t1 = fmaxf(t1, fmaxf(c[nf][2], c[nf][3]));
        }
        t0 = fmaxf(t0, __shfl_xor_sync(0xffffffffu, t0, 1));
        t0 = fmaxf(t0, __shfl_xor_sync(0xffffffffu, t0, 2));
        t1 = fmaxf(t1, __shfl_xor_sync(0xffffffffu, t1, 1));
        t1 = fmaxf(t1, __shfl_xor_sync(0xffffffffu, t1, 2));
        if (tig == 0) { wmx[half * 64 + r0] = t0; wmx[half * 64 + r1] = t1; }
        __syncthreads();                                    // (C)

        // stage V tile [d][key-interleaved 64] — overlaps softmax math
#pragma unroll
        for (int it = 0; it < 8; it++) {
            int f = it * 256 + tid;
            int d = f >> 4, gr = f & 15;
            cpa16(sKV + (uint32_t)((d * VST + gr * 4) * 4),
                  Vb + (size_t)d * TKP + kt * 64 + gr * 4);
        }
        asm volatile("cp.async.commit_group;");

        float mn0 = fmaxf(m0r, fmaxf(wmx[r0], wmx[64 + r0]));
        float mn1 = fmaxf(m1r, fmaxf(wmx[r1], wmx[64 + r1]));
        float sc0 = __expf(m0r - mn0);
        float sc1 = __expf(m1r - mn1);
        m0r = mn0; m1r = mn1;
        sp0 *= sc0; sx0 *= sc0; sp1 *= sc1; sx1 *= sc1;
#pragma unroll
        for (int nf = 0; nf < 8; nf++) {
            Om[nf][0] *= sc0; Om[nf][1] *= sc0; Om[nf][2] *= sc1; Om[nf][3] *= sc1;
            Ox[nf][0] *= sc0; Ox[nf][1] *= sc0; Ox[nf][2] *= sc1; Ox[nf][3] *= sc1;
        }
        float lp0 = 0.f, lx0 = 0.f, lp1 = 0.f, lx1 = 0.f;
#pragma unroll
        for (int nf = 0; nf < 4; nf++) {
            int kl = n0 + nf * 8 + 2 * tig;
            int kg = kt * 64 + kl;
            float p0 = f2tf(__expf(c[nf][0] - mn0));
            float p1 = f2tf(__expf(c[nf][1] - mn0));
            float p2 = f2tf(__expf(c[nf][2] - mn1));
            float p3 = f2tf(__expf(c[nf][3] - mn1));
            *(float2*)(Ps + r0 * PST + kl) = make_float2(p0, p1);
            *(float2*)(Ps + r1 * PST + kl) = make_float2(p2, p3);
            if (kg     <= kmax0) lp0 += p0; else lx0 += p0;
            if (kg + 1 <= kmax0) lp0 += p1; else lx0 += p1;
            if (kg     <= kmax1) lp1 += p2; else lx1 += p2;
            if (kg + 1 <= kmax1) lp1 += p3; else lx1 += p3;
        }
        lp0 += __shfl_xor_sync(0xffffffffu, lp0, 1); lp0 += __shfl_xor_sync(0xffffffffu, lp0, 2);
        lx0 += __shfl_xor_sync(0xffffffffu, lx0, 1); lx0 += __shfl_xor_sync(0xffffffffu, lx0, 2);
        lp1 += __shfl_xor_sync(0xffffffffu, lp1, 1); lp1 += __shfl_xor_sync(0xffffffffu, lp1, 2);
        lx1 += __shfl_xor_sync(0xffffffffu, lx1, 1); lx1 += __shfl_xor_sync(0xffffffffu, lx1, 2);
        if (tig == 0) {
            wsp[half * 64 + r0] = lp0; wsp[half * 64 + r1] = lp1;
            wsx[half * 64 + r0] = lx0; wsx[half * 64 + r1] = lx1;
        }
        asm volatile("cp.async.wait_group 0;");
        __syncthreads();                                    // (D)

        sp0 += wsp[r0] + wsp[64 + r0];
        sp1 += wsp[r1] + wsp[64 + r1];
        sx0 += wsx[r0] + wsx[64 + r0];
        sx1 += wsx[r1] + wsx[64 + r1];

        // PV: B-frag = one LDS.64 from transposed-interleaved V
        if (kt < bt) {
#pragma unroll
            for (int ks = 0; ks < 8; ks++) {
                int k0 = ks * 8;
                float a0 = Ps[r0 * PST + k0 + tig];
                float a1 = Ps[r1 * PST + k0 + tig];
                float a2 = Ps[r0 * PST + k0 + tig + 4];
                float a3 = Ps[r1 * PST + k0 + tig + 4];
#pragma unroll
                for (int nf = 0; nf < 8; nf++) {
                    float2 bv = *(const float2*)(KVs + (cc + nf * 8 + gid) * VST + k0 + 2 * tig);
                    mma8(Om[nf], a0, a1, a2, a3, bv.x, bv.y);
                }
            }
        } else if (kt > bt) {
#pragma unroll
            for (int ks = 0; ks < 8; ks++) {
                int k0 = ks * 8;
                float a0 = Ps[r0 * PST + k0 + tig];
                float a1 = Ps[r1 * PST + k0 + tig];
                float a2 = Ps[r0 * PST + k0 + tig + 4];
                float a3 = Ps[r1 * PST + k0 + tig + 4];
#pragma unroll
                for (int nf = 0; nf < 8; nf++) {
                    float2 bv = *(const float2*)(KVs + (cc + nf * 8 + gid) * VST + k0 + 2 * tig);
                    mma8(Ox[nf], a0, a1, a2, a3, bv.x, bv.y);
                }
            }
        } else {
#pragma unroll
            for (int ks = 0; ks < 8; ks++) {
                int k0 = ks * 8;
                int kgA = kt * 64 + k0 + tig;
                int kgB = kgA + 4;
                float a0 = Ps[r0 * PST + k0 + tig];
                float a1 = Ps[r1 * PST + k0 + tig];
                float a2 = Ps[r0 * PST + k0 + tig + 4];
                float a3 = Ps[r1 * PST + k0 + tig + 4];
                float m0_ = (kgA <= kmax0) ? a0 : 0.f;
                float m1_ = (kgA <= kmax1) ? a1 : 0.f;
                float m2_ = (kgB <= kmax0) ? a2 : 0.f;
                float m3_ = (kgB <= kmax1) ? a3 : 0.f;
                float x0_ = a0 - m0_, x1_ = a1 - m1_, x2_ = a2 - m2_, x3_ = a3 - m3_;
#pragma unroll
                for (int nf = 0; nf < 8; nf++) {
                    float2 bv = *(const float2*)(KVs + (cc + nf * 8 + gid) * VST + k0 + 2 * tig);
                    mma8(Om[nf], m0_, m1_, m2_, m3_, bv.x, bv.y);
                    mma8(Ox[nf], x0_, x1_, x2_, x3_, bv.x, bv.y);
                }
            }
        }
    }

    // epilogue: atomic adds into zeroed Out
    float alpha = 1.f / (1.f + __expf(-__ldg(alpha_p)));
    float wp0 = alpha / sp0;
    float wp1 = alpha / sp1;
    float wu0 = (1.f - alpha) / (sp0 + sx0);
    float wu1 = (1.f - alpha) / (sp1 + sx1);

    int qg0 = Q0 + r0, qg1 = Q0 + r1;
    float* O0 = Out + ((size_t)b * T_ + qg0) * HD;
    float* O1 = Out + ((size_t)b * T_ + qg1) * HD;
    float* U0 = Out + ((size_t)b * T_ + (T_ - 1 - qg0)) * HD;
    float* U1 = Out + ((size_t)b * T_ + (T_ - 1 - qg1)) * HD;
#pragma unroll
    for (int nf = 0; nf < 8; nf++) {
        int col = cc + nf * 8 + 2 * tig;
        atomicAdd(O0 + col,     Om[nf][0] * wp0);
        atomicAdd(O0 + col + 1, Om[nf][1] * wp0);
        atomicAdd(O1 + col,     Om[nf][2] * wp1);
        atomicAdd(O1 + col + 1, Om[nf][3] * wp1);
        atomicAdd(U0 + col,     (Om[nf][0] + Ox[nf][0]) * wu0);
        atomicAdd(U0 + col + 1, (Om[nf][1] + Ox[nf][1]) * wu0);
        atomicAdd(U1 + col,     (Om[nf][2] + Ox[nf][2]) * wu1);
        atomicAdd(U1 + col + 1, (Om[nf][3] + Ox[nf][3]) * wu1);
    }
}

// ---------------- launch ----------------
extern "C" void kernel_launch(void* const* d_in, const int* in_sizes, int n_in,
                              void* d_out, int out_size) {
    const float* x  = (const float*)d_in[0];
    const float* Wq = (const float*)d_in[1];
    const float* Wk = (const float*)d_in[2];
    const float* Wv = (const float*)d_in[3];
    const float* fa = (const float*)d_in[9];
    float* out = (float*)d_out;

    const int PROJ_SMEM = (2 * ABUF + 2 * BBUF) * 4;                        // 69632 B
    const int ATTN_SMEM = (64 * QST + 9216 + 64 * PST + 3 * 128) * 4;       // 90624 B
    cudaFuncSetAttribute(proj_k, cudaFuncAttributeMaxDynamicSharedMemorySize, PROJ_SMEM);
    cudaFuncSetAttribute(attn_k, cudaFuncAttributeMaxDynamicSharedMemorySize, ATTN_SMEM);

    theta_k<<<1, 64>>>();
    rope_table_k<<<T_, 64>>>();
    cvtW_k<<<192, 256>>>(Wq, Wk, Wv);
    pool_x_k<<<(B_ * TKP * 128) / 256, 256>>>(x);
    proj_k<<<192, 256, PROJ_SMEM>>>(x);
    ropep_k<<<(B_ * T_ * 8) / 256, 256>>>(0);
    ropep_k<<<(B_ * TKP * 8) / 256, 256>>>(1);
    zero_k<<<(B_ * T_ * HD / 4) / 256, 256>>>(out);
    vtr_k<<<64, 256>>>();
    attn_k<<<dim3(T_ / 64, B_), 256, ATTN_SMEM>>>(fa, out);
}

// round 12
// speedup vs baseline: 1.0313x; 1.0313x over previous
#include <cuda_runtime.h>
#include <cstdint>

#define B_  4
#define T_  4096
#define TKP 1024
#define DM  1024
#define HD  128
#define SCALE_INV 0.08838834764831845f   // 1/sqrt(128)

// ---------------- static device scratch ----------------
__device__ float  g_xp[B_ * TKP * DM];   // pooled x: tf32-rounded, DM k-interleaved per 8-block
__device__ float  g_Q [B_ * T_  * HD];   // roped+scaled+rounded, d-interleaved per 8-block
__device__ float  g_K [B_ * TKP * HD];   // roped+rounded, d-interleaved per 8-block
__device__ float  g_V [B_ * TKP * HD];   // normal layout, tf32-rounded
__device__ float  g_Wt[3 * DM * HD];     // tf32 weights, layout [which][kblk][n][8 interleaved]
__device__ float  g_cos[T_ * 64];
__device__ float  g_sin[T_ * 64];
__device__ double g_theta[64];

// ---------------- helpers ----------------
__device__ __forceinline__ unsigned f2t(float x) {
    unsigned r; asm("cvt.rna.tf32.f32 %0, %1;" : "=r"(r) : "f"(x)); return r;
}
__device__ __forceinline__ float f2tf(float x) { return __uint_as_float(f2t(x)); }
__device__ __forceinline__ float4 f2tf4(float4 v) {
    return make_float4(f2tf(v.x), f2tf(v.y), f2tf(v.z), f2tf(v.w));
}
__device__ __forceinline__ void mma8(float* d,
                                     float a0, float a1, float a2, float a3,
                                     float b0, float b1) {
    asm volatile("mma.sync.aligned.m16n8k8.row.col.f32.tf32.tf32.f32 "
                 "{%0,%1,%2,%3},{%4,%5,%6,%7},{%8,%9},{%0,%1,%2,%3};"
                 : "+f"(d[0]), "+f"(d[1]), "+f"(d[2]), "+f"(d[3])
                 : "r"(__float_as_uint(a0)), "r"(__float_as_uint(a1)),
                   "r"(__float_as_uint(a2)), "r"(__float_as_uint(a3)),
                   "r"(__float_as_uint(b0)), "r"(__float_as_uint(b1)));
}
__device__ __forceinline__ void cpa16(uint32_t dst, const void* src) {
    asm volatile("cp.async.cg.shared.global [%0], [%1], 16;" :: "r"(dst), "l"(src));
}

// ---------------- RoPE tables (proven pair) ----------------
__global__ void theta_k() {
    int i = threadIdx.x;
    g_theta[i] = exp(((double)(-i) / 64.0) * log(10000.0));
}
__global__ void rope_table_k() {
    int t = blockIdx.x, i = threadIdx.x;
    float thf = (float)g_theta[i];
    float arg = (float)t * thf;          // fp32 product, matching reference
    const double TWO_PI  = 6.283185307179586476925286766559;
    const double INV2PI  = 0.15915494309189533576888376337251;
    double da = (double)arg;
    double k  = rint(da * INV2PI);
    float  r  = (float)(da - k * TWO_PI);
    g_cos[t * 64 + i] = cosf(r);
    g_sin[t * 64 + i] = sinf(r);
}

// ---------------- weights -> tf32, layout [which][kblk][n][8 interleaved] ----------------
__global__ void cvtW_k(const float* __restrict__ Wq, const float* __restrict__ Wk,
                       const float* __restrict__ Wv) {
    int g = blockIdx.x * 256 + threadIdx.x;   // 3*128*128 = 49152 threads
    int n = g & 127;
    int kb = (g >> 7) & 127;
    int which = g >> 14;
    const float* W = (which == 0) ? Wq : (which == 1 ? Wk : Wv);
    float w[8];
#pragma unroll
    for (int j = 0; j < 8; j++) w[j] = f2tf(W[(size_t)(kb * 8 + j) * HD + n]);
    float* dst = g_Wt + (((size_t)which * 128 + kb) * 128 + n) * 8;
    *(float4*)(dst)     = make_float4(w[0], w[4], w[1], w[5]);
    *(float4*)(dst + 4) = make_float4(w[2], w[6], w[3], w[7]);
}

// ---------------- stride-4 mean pool: tf32-round + k-interleave the DM dim ----------------
__global__ void pool_x_k(const float* __restrict__ x) {
    int g  = blockIdx.x * 256 + threadIdx.x;     // B*TKP*128 threads, one 8-block each
    int d8 = g & 127;
    int row = g >> 7;                            // b*1024 + tp
    int b   = row >> 10, tp = row & 1023;
    const float* base = x + ((size_t)b * T_ + 4 * tp) * DM + d8 * 8;
    float v[8] = {0.f, 0.f, 0.f, 0.f, 0.f, 0.f, 0.f, 0.f};
#pragma unroll
    for (int r = 0; r < 4; r++) {
        float4 a = *(const float4*)(base + (size_t)r * DM);
        float4 c = *(const float4*)(base + (size_t)r * DM + 4);
        v[0] += a.x; v[1] += a.y; v[2] += a.z; v[3] += a.w;
        v[4] += c.x; v[5] += c.y; v[6] += c.z; v[7] += c.w;
    }
#pragma unroll
    for (int j = 0; j < 8; j++) v[j] = f2tf(v[j] * 0.25f);
    float* dst = g_xp + (size_t)row * DM + d8 * 8;
    *(float4*)(dst)     = make_float4(v[0], v[4], v[1], v[5]);
    *(float4*)(dst + 4) = make_float4(v[2], v[6], v[3], v[7]);
}

// ---------------- projection GEMM with fused RoPE epilogue for Q/K ----------------
#define AST 36
#define ABUF (128 * AST)
#define BBUF 4096                         // 4 kblk x 128 n x 8
// psm total = 2*ABUF + 2*BBUF = 17408 floats; epilogue reuses it as C-tile [128][136].
__global__ void __launch_bounds__(256, 2) proj_k(const float* __restrict__ x) {
    extern __shared__ __align__(16) float psm[];
    float* As = psm;
    float* Bs = psm + 2 * ABUF;

    int bid = blockIdx.x;
    const float* A; const float* Wm; float* Cm; int m0;
    bool isQ = false, isV = false;
    if (bid < 128)      { A = x;    Wm = g_Wt;                Cm = g_Q; m0 = bid * 128; isQ = true; }
    else if (bid < 160) { A = g_xp; Wm = g_Wt + DM * HD;      Cm = g_K; m0 = (bid - 128) * 128; }
    else                { A = g_xp; Wm = g_Wt + 2 * DM * HD;  Cm = g_V; m0 = (bid - 160) * 128; isV = true; }

    int tid  = threadIdx.x;
    int lane = tid & 31, wid = tid >> 5;
    int gid  = lane >> 2, tig = lane & 3;
    int wm = wid >> 1, wn = wid & 1;

    uint32_t sA = (uint32_t)__cvta_generic_to_shared(As);
    uint32_t sB = (uint32_t)__cvta_generic_to_shared(Bs);
    int ar = tid >> 3, ac = tid & 7;

    auto stage = [&](int kb, int buf) {
#pragma unroll
        for (int it = 0; it < 4; it++) {
            int r = ar + it * 32;
            cpa16(sA + (uint32_t)((buf * ABUF + r * AST + ac * 4) * 4),
                  A + (size_t)(m0 + r) * DM + kb * 32 + ac * 4);
        }
#pragma unroll
        for (int it = 0; it < 4; it++) {
            int idx = it * 256 + tid;
            cpa16(sB + (uint32_t)((buf * BBUF + idx * 4) * 4),
                  Wm + (size_t)kb * 4096 + idx * 4);
        }
        asm volatile("cp.async.commit_group;");
    };

    float C[2][8][4];
#pragma unroll
    for (int mf = 0; mf < 2; mf++)
#pragma unroll
        for (int nf = 0; nf < 8; nf++)
#pragma unroll
            for (int j = 0; j < 4; j++) C[mf][nf][j] = 0.f;

    stage(0, 0);
    stage(1, 1);

    for (int kb = 0; kb < 32; kb++) {
        if (kb < 30) { asm volatile("cp.async.wait_group 1;"); }
        else         { asm volatile("cp.async.wait_group 0;"); }
        __syncthreads();
        const float* Ab = As + (kb & 1) * ABUF;
        const float* Bb = Bs + (kb & 1) * BBUF;
#pragma unroll
        for (int ks = 0; ks < 4; ks++) {
            int k0 = ks * 8;
            float ah[2][4];
            if (isQ) {
#pragma unroll
                for (int mf = 0; mf < 2; mf++) {
                    int mb = wm * 32 + mf * 16;
                    ah[mf][0] = f2tf(Ab[(mb + gid)     * AST + k0 + tig]);
                    ah[mf][1] = f2tf(Ab[(mb + gid + 8) * AST + k0 + tig]);
                    ah[mf][2] = f2tf(Ab[(mb + gid)     * AST + k0 + tig + 4]);
                    ah[mf][3] = f2tf(Ab[(mb + gid + 8) * AST + k0 + tig + 4]);
                }
            } else {
#pragma unroll
                for (int mf = 0; mf < 2; mf++) {
                    int mb = wm * 32 + mf * 16;
                    float2 a0 = *(const float2*)(Ab + (mb + gid)     * AST + k0 + 2 * tig);
                    float2 a1 = *(const float2*)(Ab + (mb + gid + 8) * AST + k0 + 2 * tig);
                    ah[mf][0] = a0.x; ah[mf][1] = a1.x; ah[mf][2] = a0.y; ah[mf][3] = a1.y;
                }
            }
#pragma unroll
            for (int nf = 0; nf < 8; nf++) {
                int nb = wn * 64 + nf * 8 + gid;
                float2 bb = *(const float2*)(Bb + (ks * 128 + nb) * 8 + 2 * tig);
#pragma unroll
                for (int mf = 0; mf < 2; mf++)
                    mma8(C[mf][nf], ah[mf][0], ah[mf][1], ah[mf][2], ah[mf][3], bb.x, bb.y);
            }
        }
        __syncthreads();
        if (kb + 2 < 32) stage(kb + 2, kb & 1);
    }

    if (isV) {
        // V: tf32-round + normal coalesced store (R7-proven)
#pragma unroll
        for (int mf = 0; mf < 2; mf++) {
            int r0 = m0 + wm * 32 + mf * 16 + gid;
#pragma unroll
            for (int nf = 0; nf < 8; nf++) {
                int col = wn * 64 + nf * 8 + 2 * tig;
                *(float2*)(Cm + (size_t)r0 * HD + col) =
                    make_float2(f2tf(C[mf][nf][0]), f2tf(C[mf][nf][1]));
                *(float2*)(Cm + (size_t)(r0 + 8) * HD + col) =
                    make_float2(f2tf(C[mf][nf][2]), f2tf(C[mf][nf][3]));
            }
        }
    } else {
        // Q/K: C-tile -> smem [128][136], then fused rope+scale+round+interleave store
        __syncthreads();     // all mma / staging use of psm done (loop's final sync passed; be safe)
#pragma unroll
        for (int mf = 0; mf < 2; mf++) {
            int rr = wm * 32 + mf * 16 + gid;
#pragma unroll
            for (int nf = 0; nf < 8; nf++) {
                int col = wn * 64 + nf * 8 + 2 * tig;
                *(float2*)(psm + rr * 136 + col)       = make_float2(C[mf][nf][0], C[mf][nf][1]);
                *(float2*)(psm + (rr + 8) * 136 + col) = make_float2(C[mf][nf][2], C[mf][nf][3]);
            }
        }
        __syncthreads();
        int mask  = isQ ? (T_ - 1) : (TKP - 1);
        float scl = isQ ? SCALE_INV : 1.f;
#pragma unroll
        for (int it = 0; it < 4; it++) {
            int id  = it * 256 + tid;        // 1024 tasks: 128 rows x 8 lower-half 8-blocks
            int row = id >> 3, b8 = id & 7;
            int pos = (m0 + row) & mask;
            float c[8], s[8], x1[8], x2[8];
            const float4* cp = (const float4*)(g_cos + pos * 64 + b8 * 8);
            const float4* sp = (const float4*)(g_sin + pos * 64 + b8 * 8);
            *(float4*)(c)     = cp[0]; *(float4*)(c + 4) = cp[1];
            *(float4*)(s)     = sp[0]; *(float4*)(s + 4) = sp[1];
            const float* pr = psm + row * 136 + b8 * 8;
            *(float4*)(x1)     = *(const float4*)(pr);
            *(float4*)(x1 + 4) = *(const float4*)(pr + 4);
            *(float4*)(x2)     = *(const float4*)(pr + 64);
            *(float4*)(x2 + 4) = *(const float4*)(pr + 68);
            float o1[8], o2[8];
#pragma unroll
            for (int j = 0; j < 8; j++) {
                o1[j] = (x1[j] * c[j] - x2[j] * s[j]) * scl;
                o2[j] = (x2[j] * c[j] + x1[j] * s[j]) * scl;
            }
            float* q = Cm + (size_t)(m0 + row) * HD + b8 * 8;
            *(float4*)(q)      = f2tf4(make_float4(o1[0], o1[4], o1[1], o1[5]));
            *(float4*)(q + 4)  = f2tf4(make_float4(o1[2], o1[6], o1[3], o1[7]));
            *(float4*)(q + 64) = f2tf4(make_float4(o2[0], o2[4], o2[1], o2[5]));
            *(float4*)(q + 68) = f2tf4(make_float4(o2[2], o2[6], o2[3], o2[7]));
        }
    }
}

// ---------------- zero output ----------------
__global__ void zero_k(float* __restrict__ out) {
    ((float4*)out)[blockIdx.x * 256 + threadIdx.x] = make_float4(0.f, 0.f, 0.f, 0.f);
}

// ---------------- flash attention: EXACT R7 version (proven 186.6) ----------
#define QST 136
#define KST 136
#define PST 68
__global__ void __launch_bounds__(256, 2) attn_k(const float* __restrict__ alpha_p,
                                                 float* __restrict__ Out)
{
    extern __shared__ __align__(16) float sm[];
    float* Qs  = sm;                        // 64 x 136
    float* KVs = Qs + 64 * QST;             // 64 x 136 (K then V)
    float* Ps  = KVs + 64 * KST;            // 64 x 68
    float* wmx = Ps + 64 * PST;             // [2][64]
    float* wsp = wmx + 128;
    float* wsx = wsp + 128;

    int tid  = threadIdx.x;
    int lane = tid & 31, wid = tid >> 5;
    int gid  = lane >> 2, tig = lane & 3;
    int rg   = wid >> 1, half = wid & 1;
    int Q0 = blockIdx.x * 64;
    int b  = blockIdx.y;
    const float* Qb = g_Q + ((size_t)b * T_ + Q0) * HD;
    const float* Kb = g_K + (size_t)b * TKP * HD;
    const float* Vb = g_V + (size_t)b * TKP * HD;

    uint32_t sQ  = (uint32_t)__cvta_generic_to_shared(Qs);
    uint32_t sKV = (uint32_t)__cvta_generic_to_shared(KVs);
    int sr = tid >> 3, sc = tid & 7;

#pragma unroll
    for (int it = 0; it < 2; it++) {
        int r = sr + it * 32;
        cpa16(sQ + (uint32_t)((r * QST + sc * 4) * 4),      Qb + (size_t)r * HD + sc * 4);
        cpa16(sQ + (uint32_t)((r * QST + 32 + sc * 4) * 4), Qb + (size_t)r * HD + 32 + sc * 4);
        cpa16(sQ + (uint32_t)((r * QST + 64 + sc * 4) * 4), Qb + (size_t)r * HD + 64 + sc * 4);
        cpa16(sQ + (uint32_t)((r * QST + 96 + sc * 4) * 4), Qb + (size_t)r * HD + 96 + sc * 4);
    }
    asm volatile("cp.async.commit_group;");

    int r0 = rg * 16 + gid, r1 = r0 + 8;
    int kmax0 = (Q0 + r0) >> 2, kmax1 = (Q0 + r1) >> 2;
    int bt = Q0 >> 8;
    int n0 = half * 32;
    int cc = half * 64;

    float m0r = -1e30f, m1r = -1e30f;
    float sp0 = 0.f, sp1 = 0.f, sx0 = 0.f, sx1 = 0.f;
    float Om[8][4], Ox[8][4];
#pragma unroll
    for (int nf = 0; nf < 8; nf++)
#pragma unroll
        for (int j = 0; j < 4; j++) { Om[nf][j] = 0.f; Ox[nf][j] = 0.f; }

    for (int kt = 0; kt < 16; kt++) {
        __syncthreads();                                    // (A)
#pragma unroll
        for (int it = 0; it < 2; it++) {
            int r = sr + it * 32;
            const float* src = Kb + (size_t)(kt * 64 + r) * HD;
            cpa16(sKV + (uint32_t)((r * KST + sc * 4) * 4),      src + sc * 4);
            cpa16(sKV + (uint32_t)((r * KST + 32 + sc * 4) * 4), src + 32 + sc * 4);
            cpa16(sKV + (uint32_t)((r * KST + 64 + sc * 4) * 4), src + 64 + sc * 4);
            cpa16(sKV + (uint32_t)((r * KST + 96 + sc * 4) * 4), src + 96 + sc * 4);
        }
        asm volatile("cp.async.commit_group;");
        asm volatile("cp.async.wait_group 0;");
        __syncthreads();                                    // (B)

        // S = Q K^T — LDS.64 frags (interleaved layouts)
        float c[4][4];
#pragma unroll
        for (int nf = 0; nf < 4; nf++)
#pragma unroll
            for (int j = 0; j < 4; j++) c[nf][j] = 0.f;
#pragma unroll
        for (int ks = 0; ks < 16; ks++) {
            int k0 = ks * 8;
            float2 qa0 = *(const float2*)(Qs + r0 * QST + k0 + 2 * tig);
            float2 qa1 = *(const float2*)(Qs + r1 * QST + k0 + 2 * tig);
#pragma unroll
            for (int nf = 0; nf < 4; nf++) {
                float2 kb2 = *(const float2*)(KVs + (n0 + nf * 8 + gid) * KST + k0 + 2 * tig);
                mma8(c[nf], qa0.x, qa1.x, qa0.y, qa1.y, kb2.x, kb2.y);
            }
        }
        float t0 = -1e30f, t1 = -1e30f;
#pragma unroll
        for (int nf = 0; nf < 4; nf++) {
            t0 = fmaxf(t0, fmaxf(c[nf][0], c[nf][1]));
            t1 = fmaxf(t1, fmaxf(c[nf][2], c[nf][3]));
        }
        t0 = fmaxf(t0, __shfl_xor_sync(0xffffffffu, t0, 1));
        t0 = fmaxf(t0, __shfl_xor_sync(0xffffffffu, t0, 2));
        t1 = fmaxf(t1, __shfl_xor_sync(0xffffffffu, t1, 1));
        t1 = fmaxf(t1, __shfl_xor_sync(0xffffffffu, t1, 2));
        if (tig == 0) { wmx[half * 64 + r0] = t0; wmx[half * 64 + r1] = t1; }
        __syncthreads();                                    // (C)

        // stage V tile (normal layout) — overlaps softmax math
#pragma unroll
        for (int it = 0; it < 8; it++) {
            int f = it * 256 + tid;
            int kr = f >> 5, d4 = f & 31;
            cpa16(sKV + (uint32_t)((kr * KST + d4 * 4) * 4),
                  Vb + (size_t)(kt * 64 + kr) * HD + d4 * 4);
        }
        asm volatile("cp.async.commit_group;");

        float mn0 = fmaxf(m0r, fmaxf(wmx[r0], wmx[64 + r0]));
        float mn1 = fmaxf(m1r, fmaxf(wmx[r1], wmx[64 + r1]));
        float sc0 = __expf(m0r - mn0);
        float sc1 = __expf(m1r - mn1);
        m0r = mn0; m1r = mn1;
        sp0 *= sc0; sx0 *= sc0; sp1 *= sc1; sx1 *= sc1;
#pragma unroll
        for (int nf = 0; nf < 8; nf++) {
            Om[nf][0] *= sc0; Om[nf][1] *= sc0; Om[nf][2] *= sc1; Om[nf][3] *= sc1;
            Ox[nf][0] *= sc0; Ox[nf][1] *= sc0; Ox[nf][2] *= sc1; Ox[nf][3] *= sc1;
        }
        float lp0 = 0.f, lx0 = 0.f, lp1 = 0.f, lx1 = 0.f;
#pragma unroll
        for (int nf = 0; nf < 4; nf++) {
            int kl = n0 + nf * 8 + 2 * tig;
            int kg = kt * 64 + kl;
            float p0 = f2tf(__expf(c[nf][0] - mn0));
            float p1 = f2tf(__expf(c[nf][1] - mn0));
            float p2 = f2tf(__expf(c[nf][2] - mn1));
            float p3 = f2tf(__expf(c[nf][3] - mn1));
            *(float2*)(Ps + r0 * PST + kl) = make_float2(p0, p1);
            *(float2*)(Ps + r1 * PST + kl) = make_float2(p2, p3);
            if (kg     <= kmax0) lp0 += p0; else lx0 += p0;
            if (kg + 1 <= kmax0) lp0 += p1; else lx0 += p1;
            if (kg     <= kmax1) lp1 += p2; else lx1 += p2;
            if (kg + 1 <= kmax1) lp1 += p3; else lx1 += p3;
        }
        lp0 += __shfl_xor_sync(0xffffffffu, lp0, 1); lp0 += __shfl_xor_sync(0xffffffffu, lp0, 2);
        lx0 += __shfl_xor_sync(0xffffffffu, lx0, 1); lx0 += __shfl_xor_sync(0xffffffffu, lx0, 2);
        lp1 += __shfl_xor_sync(0xffffffffu, lp1, 1); lp1 += __shfl_xor_sync(0xffffffffu, lp1, 2);
        lx1 += __shfl_xor_sync(0xffffffffu, lx1, 1); lx1 += __shfl_xor_sync(0xffffffffu, lx1, 2);
        if (tig == 0) {
            wsp[half * 64 + r0] = lp0; wsp[half * 64 + r1] = lp1;
            wsx[half * 64 + r0] = lx0; wsx[half * 64 + r1] = lx1;
        }
        asm volatile("cp.async.wait_group 0;");
        __syncthreads();                                    // (D)

        sp0 += wsp[r0] + wsp[64 + r0];
        sp1 += wsp[r1] + wsp[64 + r1];
        sx0 += wsx[r0] + wsx[64 + r0];
        sx1 += wsx[r1] + wsx[64 + r1];

        if (kt < bt) {
#pragma unroll
            for (int ks = 0; ks < 8; ks++) {
                int k0 = ks * 8;
                float a0 = Ps[r0 * PST + k0 + tig];
                float a1 = Ps[r1 * PST + k0 + tig];
                float a2 = Ps[r0 * PST + k0 + tig + 4];
                float a3 = Ps[r1 * PST + k0 + tig + 4];
#pragma unroll
                for (int nf = 0; nf < 8; nf++) {
                    const float* vp = KVs + (k0 + tig) * KST + cc + nf * 8 + gid;
                    mma8(Om[nf], a0, a1, a2, a3, vp[0], vp[4 * KST]);
                }
            }
        } else if (kt > bt) {
#pragma unroll
            for (int ks = 0; ks < 8; ks++) {
                int k0 = ks * 8;
                float a0 = Ps[r0 * PST + k0 + tig];
                float a1 = Ps[r1 * PST + k0 + tig];
                float a2 = Ps[r0 * PST + k0 + tig + 4];
                float a3 = Ps[r1 * PST + k0 + tig + 4];
#pragma unroll
                for (int nf = 0; nf < 8; nf++) {
                    const float* vp = KVs + (k0 + tig) * KST + cc + nf * 8 + gid;
                    mma8(Ox[nf], a0, a1, a2, a3, vp[0], vp[4 * KST]);
                }
            }
        } else {
#pragma unroll
            for (int ks = 0; ks < 8; ks++) {
                int k0 = ks * 8;
                int kgA = kt * 64 + k0 + tig;
                int kgB = kgA + 4;
                float a0 = Ps[r0 * PST + k0 + tig];
                float a1 = Ps[r1 * PST + k0 + tig];
                float a2 = Ps[r0 * PST + k0 + tig + 4];
                float a3 = Ps[r1 * PST + k0 + tig + 4];
                float m0_ = (kgA <= kmax0) ? a0 : 0.f;
                float m1_ = (kgA <= kmax1) ? a1 : 0.f;
                float m2_ = (kgB <= kmax0) ? a2 : 0.f;
                float m3_ = (kgB <= kmax1) ? a3 : 0.f;
                float x0_ = a0 - m0_, x1_ = a1 - m1_, x2_ = a2 - m2_, x3_ = a3 - m3_;
#pragma unroll
                for (int nf = 0; nf < 8; nf++) {
                    const float* vp = KVs + (k0 + tig) * KST + cc + nf * 8 + gid;
                    float b0 = vp[0], b1 = vp[4 * KST];
                    mma8(Om[nf], m0_, m1_, m2_, m3_, b0, b1);
                    mma8(Ox[nf], x0_, x1_, x2_, x3_, b0, b1);
                }
            }
        }
    }

    // epilogue: atomic adds into zeroed Out
    float alpha = 1.f / (1.f + __expf(-__ldg(alpha_p)));
    float wp0 = alpha / sp0;
    float wp1 = alpha / sp1;
    float wu0 = (1.f - alpha) / (sp0 + sx0);
    float wu1 = (1.f - alpha) / (sp1 + sx1);

    int qg0 = Q0 + r0, qg1 = Q0 + r1;
    float* O0 = Out + ((size_t)b * T_ + qg0) * HD;
    float* O1 = Out + ((size_t)b * T_ + qg1) * HD;
    float* U0 = Out + ((size_t)b * T_ + (T_ - 1 - qg0)) * HD;
    float* U1 = Out + ((size_t)b * T_ + (T_ - 1 - qg1)) * HD;
#pragma unroll
    for (int nf = 0; nf < 8; nf++) {
        int col = cc + nf * 8 + 2 * tig;
        atomicAdd(O0 + col,     Om[nf][0] * wp0);
        atomicAdd(O0 + col + 1, Om[nf][1] * wp0);
        atomicAdd(O1 + col,     Om[nf][2] * wp1);
        atomicAdd(O1 + col + 1, Om[nf][3] * wp1);
        atomicAdd(U0 + col,     (Om[nf][0] + Ox[nf][0]) * wu0);
        atomicAdd(U0 + col + 1, (Om[nf][1] + Ox[nf][1]) * wu0);
        atomicAdd(U1 + col,     (Om[nf][2] + Ox[nf][2]) * wu1);
        atomicAdd(U1 + col + 1, (Om[nf][3] + Ox[nf][3]) * wu1);
    }
}

// ---------------- launch ----------------
extern "C" void kernel_launch(void* const* d_in, const int* in_sizes, int n_in,
                              void* d_out, int out_size) {
    const float* x  = (const float*)d_in[0];
    const float* Wq = (const float*)d_in[1];
    const float* Wk = (const float*)d_in[2];
    const float* Wv = (const float*)d_in[3];
    const float* fa = (const float*)d_in[9];
    float* out = (float*)d_out;

    const int PROJ_SMEM = (2 * ABUF + 2 * BBUF) * 4;                        // 69632 B
    const int ATTN_SMEM = (64 * QST + 64 * KST + 64 * PST + 3 * 128) * 4;   // 88576 B
    cudaFuncSetAttribute(proj_k, cudaFuncAttributeMaxDynamicSharedMemorySize, PROJ_SMEM);
    cudaFuncSetAttribute(attn_k, cudaFuncAttributeMaxDynamicSharedMemorySize, ATTN_SMEM);

    theta_k<<<1, 64>>>();
    rope_table_k<<<T_, 64>>>();
    cvtW_k<<<192, 256>>>(Wq, Wk, Wv);
    pool_x_k<<<(B_ * TKP * 128) / 256, 256>>>(x);
    proj_k<<<192, 256, PROJ_SMEM>>>(x);
    zero_k<<<(B_ * T_ * HD / 4) / 256, 256>>>(out);
    attn_k<<<dim3(T_ / 64, B_), 256, ATTN_SMEM>>>(fa, out);
}

// round 13
// speedup vs baseline: 1.1510x; 1.1161x over previous
#include <cuda_runtime.h>
#include <cuda_fp16.h>
#include <cstdint>

#define B_  4
#define T_  4096
#define TKP 1024
#define DM  1024
#define HD  128
#define SCALE_INV 0.08838834764831845f   // 1/sqrt(128)

// ---------------- static device scratch ----------------
__device__ float  g_xp[B_ * TKP * DM];   // pooled x: tf32-rounded, DM k-interleaved per 8-block
__device__ float  g_Q [B_ * T_  * HD];   // proj output, plain fp32
__device__ float  g_K [B_ * TKP * HD];   // proj output, plain fp32
__device__ float  g_V [B_ * TKP * HD];   // proj output, plain fp32
__device__ float  g_Wt[3 * DM * HD];     // tf32 weights, layout [which][kblk][n][8 interleaved]
__device__ __half g_Qh[B_ * T_  * HD];   // roped+scaled fp16, pair-interleaved per 16-block
__device__ __half g_Kh[B_ * TKP * HD];   // roped fp16, pair-interleaved per 16-block
__device__ __half2 g_V2[B_ * (TKP / 2) * HD];  // [b][key-pair][d] packed half2(k_even, k_odd)
__device__ float  g_cos[T_ * 64];
__device__ float  g_sin[T_ * 64];
__device__ double g_theta[64];

// ---------------- helpers ----------------
__device__ __forceinline__ unsigned f2t(float x) {
    unsigned r; asm("cvt.rna.tf32.f32 %0, %1;" : "=r"(r) : "f"(x)); return r;
}
__device__ __forceinline__ float f2tf(float x) { return __uint_as_float(f2t(x)); }
__device__ __forceinline__ float4 f2tf4(float4 v) {
    return make_float4(f2tf(v.x), f2tf(v.y), f2tf(v.z), f2tf(v.w));
}
__device__ __forceinline__ void mma8(float* d,
                                     float a0, float a1, float a2, float a3,
                                     float b0, float b1) {
    asm volatile("mma.sync.aligned.m16n8k8.row.col.f32.tf32.tf32.f32 "
                 "{%0,%1,%2,%3},{%4,%5,%6,%7},{%8,%9},{%0,%1,%2,%3};"
                 : "+f"(d[0]), "+f"(d[1]), "+f"(d[2]), "+f"(d[3])
                 : "r"(__float_as_uint(a0)), "r"(__float_as_uint(a1)),
                   "r"(__float_as_uint(a2)), "r"(__float_as_uint(a3)),
                   "r"(__float_as_uint(b0)), "r"(__float_as_uint(b1)));
}
__device__ __forceinline__ void mma16h(float* d,
                                       unsigned a0, unsigned a1, unsigned a2, unsigned a3,
                                       unsigned b0, unsigned b1) {
    asm volatile("mma.sync.aligned.m16n8k16.row.col.f32.f16.f16.f32 "
                 "{%0,%1,%2,%3},{%4,%5,%6,%7},{%8,%9},{%0,%1,%2,%3};"
                 : "+f"(d[0]), "+f"(d[1]), "+f"(d[2]), "+f"(d[3])
                 : "r"(a0), "r"(a1), "r"(a2), "r"(a3), "r"(b0), "r"(b1));
}
__device__ __forceinline__ void cpa16(uint32_t dst, const void* src) {
    asm volatile("cp.async.cg.shared.global [%0], [%1], 16;" :: "r"(dst), "l"(src));
}

// ---------------- RoPE tables (proven pair) ----------------
__global__ void theta_k() {
    int i = threadIdx.x;
    g_theta[i] = exp(((double)(-i) / 64.0) * log(10000.0));
}
__global__ void rope_table_k() {
    int t = blockIdx.x, i = threadIdx.x;
    float thf = (float)g_theta[i];
    float arg = (float)t * thf;          // fp32 product, matching reference
    const double TWO_PI  = 6.283185307179586476925286766559;
    const double INV2PI  = 0.15915494309189533576888376337251;
    double da = (double)arg;
    double k  = rint(da * INV2PI);
    float  r  = (float)(da - k * TWO_PI);
    g_cos[t * 64 + i] = cosf(r);
    g_sin[t * 64 + i] = sinf(r);
}

// ---------------- weights -> tf32, layout [which][kblk][n][8 interleaved] ----------------
__global__ void cvtW_k(const float* __restrict__ Wq, const float* __restrict__ Wk,
                       const float* __restrict__ Wv) {
    int g = blockIdx.x * 256 + threadIdx.x;
    int n = g & 127;
    int kb = (g >> 7) & 127;
    int which = g >> 14;
    const float* W = (which == 0) ? Wq : (which == 1 ? Wk : Wv);
    float w[8];
#pragma unroll
    for (int j = 0; j < 8; j++) w[j] = f2tf(W[(size_t)(kb * 8 + j) * HD + n]);
    float* dst = g_Wt + (((size_t)which * 128 + kb) * 128 + n) * 8;
    *(float4*)(dst)     = make_float4(w[0], w[4], w[1], w[5]);
    *(float4*)(dst + 4) = make_float4(w[2], w[6], w[3], w[7]);
}

// ---------------- stride-4 mean pool: tf32-round + k-interleave the DM dim ----------------
__global__ void pool_x_k(const float* __restrict__ x) {
    int g  = blockIdx.x * 256 + threadIdx.x;
    int d8 = g & 127;
    int row = g >> 7;
    int b   = row >> 10, tp = row & 1023;
    const float* base = x + ((size_t)b * T_ + 4 * tp) * DM + d8 * 8;
    float v[8] = {0.f, 0.f, 0.f, 0.f, 0.f, 0.f, 0.f, 0.f};
#pragma unroll
    for (int r = 0; r < 4; r++) {
        float4 a = *(const float4*)(base + (size_t)r * DM);
        float4 c = *(const float4*)(base + (size_t)r * DM + 4);
        v[0] += a.x; v[1] += a.y; v[2] += a.z; v[3] += a.w;
        v[4] += c.x; v[5] += c.y; v[6] += c.z; v[7] += c.w;
    }
#pragma unroll
    for (int j = 0; j < 8; j++) v[j] = f2tf(v[j] * 0.25f);
    float* dst = g_xp + (size_t)row * DM + d8 * 8;
    *(float4*)(dst)     = make_float4(v[0], v[4], v[1], v[5]);
    *(float4*)(dst + 4) = make_float4(v[2], v[6], v[3], v[7]);
}

// ---------------- projection GEMM (R7-proven; V stored plain fp32) ----------------
#define AST 36
#define ABUF (128 * AST)
#define BBUF 4096
__global__ void __launch_bounds__(256, 2) proj_k(const float* __restrict__ x) {
    extern __shared__ __align__(16) float psm[];
    float* As = psm;
    float* Bs = psm + 2 * ABUF;

    int bid = blockIdx.x;
    const float* A; const float* Wm; float* Cm; int m0;
    bool isQ = false;
    if (bid < 128)      { A = x;    Wm = g_Wt;                Cm = g_Q; m0 = bid * 128; isQ = true; }
    else if (bid < 160) { A = g_xp; Wm = g_Wt + DM * HD;      Cm = g_K; m0 = (bid - 128) * 128; }
    else                { A = g_xp; Wm = g_Wt + 2 * DM * HD;  Cm = g_V; m0 = (bid - 160) * 128; }

    int tid  = threadIdx.x;
    int lane = tid & 31, wid = tid >> 5;
    int gid  = lane >> 2, tig = lane & 3;
    int wm = wid >> 1, wn = wid & 1;

    uint32_t sA = (uint32_t)__cvta_generic_to_shared(As);
    uint32_t sB = (uint32_t)__cvta_generic_to_shared(Bs);
    int ar = tid >> 3, ac = tid & 7;

    auto stage = [&](int kb, int buf) {
#pragma unroll
        for (int it = 0; it < 4; it++) {
            int r = ar + it * 32;
            cpa16(sA + (uint32_t)((buf * ABUF + r * AST + ac * 4) * 4),
                  A + (size_t)(m0 + r) * DM + kb * 32 + ac * 4);
        }
#pragma unroll
        for (int it = 0; it < 4; it++) {
            int idx = it * 256 + tid;
            cpa16(sB + (uint32_t)((buf * BBUF + idx * 4) * 4),
                  Wm + (size_t)kb * 4096 + idx * 4);
        }
        asm volatile("cp.async.commit_group;");
    };

    float C[2][8][4];
#pragma unroll
    for (int mf = 0; mf < 2; mf++)
#pragma unroll
        for (int nf = 0; nf < 8; nf++)
#pragma unroll
            for (int j = 0; j < 4; j++) C[mf][nf][j] = 0.f;

    stage(0, 0);
    stage(1, 1);

    for (int kb = 0; kb < 32; kb++) {
        if (kb < 30) { asm volatile("cp.async.wait_group 1;"); }
        else         { asm volatile("cp.async.wait_group 0;"); }
        __syncthreads();
        const float* Ab = As + (kb & 1) * ABUF;
        const float* Bb = Bs + (kb & 1) * BBUF;
#pragma unroll
        for (int ks = 0; ks < 4; ks++) {
            int k0 = ks * 8;
            float ah[2][4];
            if (isQ) {
#pragma unroll
                for (int mf = 0; mf < 2; mf++) {
                    int mb = wm * 32 + mf * 16;
                    ah[mf][0] = f2tf(Ab[(mb + gid)     * AST + k0 + tig]);
                    ah[mf][1] = f2tf(Ab[(mb + gid + 8) * AST + k0 + tig]);
                    ah[mf][2] = f2tf(Ab[(mb + gid)     * AST + k0 + tig + 4]);
                    ah[mf][3] = f2tf(Ab[(mb + gid + 8) * AST + k0 + tig + 4]);
                }
            } else {
#pragma unroll
                for (int mf = 0; mf < 2; mf++) {
                    int mb = wm * 32 + mf * 16;
                    float2 a0 = *(const float2*)(Ab + (mb + gid)     * AST + k0 + 2 * tig);
                    float2 a1 = *(const float2*)(Ab + (mb + gid + 8) * AST + k0 + 2 * tig);
                    ah[mf][0] = a0.x; ah[mf][1] = a1.x; ah[mf][2] = a0.y; ah[mf][3] = a1.y;
                }
            }
#pragma unroll
            for (int nf = 0; nf < 8; nf++) {
                int nb = wn * 64 + nf * 8 + gid;
                float2 bb = *(const float2*)(Bb + (ks * 128 + nb) * 8 + 2 * tig);
#pragma unroll
                for (int mf = 0; mf < 2; mf++)
                    mma8(C[mf][nf], ah[mf][0], ah[mf][1], ah[mf][2], ah[mf][3], bb.x, bb.y);
            }
        }
        __syncthreads();
        if (kb + 2 < 32) stage(kb + 2, kb & 1);
    }

#pragma unroll
    for (int mf = 0; mf < 2; mf++) {
        int r0 = m0 + wm * 32 + mf * 16 + gid;
#pragma unroll
        for (int nf = 0; nf < 8; nf++) {
            int col = wn * 64 + nf * 8 + 2 * tig;
            *(float2*)(Cm + (size_t)r0 * HD + col)       = make_float2(C[mf][nf][0], C[mf][nf][1]);
            *(float2*)(Cm + (size_t)(r0 + 8) * HD + col) = make_float2(C[mf][nf][2], C[mf][nf][3]);
        }
    }
}

// ---------------- RoPE -> fp16, pair-interleaved per 16-block ----------------
// thread: row = g>>2, blk = g&3 (lower-half 16-block); partner at d+64.
__global__ void ropeh_k(int which) {
    const float* X = which ? g_K : g_Q;
    __half* Xh     = which ? g_Kh : g_Qh;
    int mask   = which ? (TKP - 1) : (T_ - 1);
    float scl  = which ? 1.f : SCALE_INV;
    int g   = blockIdx.x * 256 + threadIdx.x;
    int blk = g & 3;
    int row = g >> 2;
    int pos = row & mask;
    float c[16], s[16], x1[16], x2[16];
    const float* cb = g_cos + pos * 64 + blk * 16;
    const float* sb = g_sin + pos * 64 + blk * 16;
#pragma unroll
    for (int q = 0; q < 4; q++) {
        *(float4*)(c + 4 * q) = *(const float4*)(cb + 4 * q);
        *(float4*)(s + 4 * q) = *(const float4*)(sb + 4 * q);
    }
    const float* p = X + (size_t)row * HD + blk * 16;
#pragma unroll
    for (int q = 0; q < 4; q++) {
        *(float4*)(x1 + 4 * q) = *(const float4*)(p + 4 * q);
        *(float4*)(x2 + 4 * q) = *(const float4*)(p + 64 + 4 * q);
    }
    float o1[16], o2[16];
#pragma unroll
    for (int j = 0; j < 16; j++) {
        o1[j] = (x1[j] * c[j] - x2[j] * s[j]) * scl;
        o2[j] = (x2[j] * c[j] + x1[j] * s[j]) * scl;
    }
    // pair-interleave: pairs [0,4,1,5,2,6,3,7]
    __half2 h1[8], h2[8];
#pragma unroll
    for (int t = 0; t < 4; t++) {
        h1[2 * t]     = __floats2half2_rn(o1[2 * t],     o1[2 * t + 1]);
        h1[2 * t + 1] = __floats2half2_rn(o1[2 * t + 8], o1[2 * t + 9]);
        h2[2 * t]     = __floats2half2_rn(o2[2 * t],     o2[2 * t + 1]);
        h2[2 * t + 1] = __floats2half2_rn(o2[2 * t + 8], o2[2 * t + 9]);
    }
    __half* dst = Xh + (size_t)row * HD + blk * 16;
    *(uint4*)(dst)      = *(uint4*)(h1);
    *(uint4*)(dst + 8)  = *(uint4*)(h1 + 4);
    *(uint4*)(dst + 64) = *(uint4*)(h2);
    *(uint4*)(dst + 72) = *(uint4*)(h2 + 4);
}

// ---------------- V -> key-pair-packed fp16: g_V2[b][kp][d] = (V[2kp][d], V[2kp+1][d]) ----
__global__ void vpack_k() {
    int g = blockIdx.x * 256 + threadIdx.x;      // B_*512*8 threads
    int oct = g & 7;                             // 16 d each
    int kp  = g >> 3;                            // global key-pair 0..2047
    const float* r0 = g_V + ((size_t)kp * 2) * HD + oct * 16;
    const float* r1 = r0 + HD;
    __half2 h[16];
#pragma unroll
    for (int q = 0; q < 4; q++) {
        float4 a = *(const float4*)(r0 + 4 * q);
        float4 b = *(const float4*)(r1 + 4 * q);
        h[4 * q + 0] = __floats2half2_rn(a.x, b.x);
        h[4 * q + 1] = __floats2half2_rn(a.y, b.y);
        h[4 * q + 2] = __floats2half2_rn(a.z, b.z);
        h[4 * q + 3] = __floats2half2_rn(a.w, b.w);
    }
    __half2* dst = g_V2 + (size_t)kp * HD + oct * 16;
    *(uint4*)(dst)      = *(uint4*)(h);
    *(uint4*)(dst + 4)  = *(uint4*)(h + 4);
    *(uint4*)(dst + 8)  = *(uint4*)(h + 8);
    *(uint4*)(dst + 12) = *(uint4*)(h + 12);
}

// ---------------- zero output ----------------
__global__ void zero_k(float* __restrict__ out) {
    ((float4*)out)[blockIdx.x * 256 + threadIdx.x] = make_float4(0.f, 0.f, 0.f, 0.f);
}

// ---------------- flash attention, fp16 datapath, R7 barrier structure ----------
#define QSTh 144     // halves per Q/K row (288 B)
#define V2ST 136     // half2 per V2 row (544 B)
#define PSTh 80      // halves per P row (160 B)
__global__ void __launch_bounds__(256, 2) attn_k(const float* __restrict__ alpha_p,
                                                 float* __restrict__ Out)
{
    extern __shared__ __align__(16) float sm[];
    float* wmx = sm;                         // [2][64]
    float* wsp = wmx + 128;
    float* wsx = wsp + 128;
    __half* Qs = (__half*)(sm + 384);        // 64 x 144 halves
    __half* Ks = Qs + 64 * QSTh;             // 64 x 144 halves (shared with V2 tile)
    __half2* V2s = (__half2*)Ks;             // 32 x 136 half2
    __half* Ps = Ks + 64 * QSTh;             // 64 x 80 halves

    int tid  = threadIdx.x;
    int lane = tid & 31, wid = tid >> 5;
    int gid  = lane >> 2, tig = lane & 3;
    int rg   = wid >> 1, half = wid & 1;
    int Q0 = blockIdx.x * 64;
    int b  = blockIdx.y;
    const __half* Qb = g_Qh + ((size_t)b * T_ + Q0) * HD;
    const __half* Kb = g_Kh + (size_t)b * TKP * HD;
    const __half2* Vb = g_V2 + (size_t)b * (TKP / 2) * HD;

    uint32_t sQ  = (uint32_t)__cvta_generic_to_shared(Qs);
    uint32_t sKV = (uint32_t)__cvta_generic_to_shared(Ks);

    // stage Q: 64 rows x 16 granules (256B data per row)
#pragma unroll
    for (int it = 0; it < 4; it++) {
        int f = it * 256 + tid;
        int r = f >> 4, g16 = f & 15;
        cpa16(sQ + (uint32_t)(r * (QSTh * 2) + g16 * 16), Qb + (size_t)r * HD + g16 * 8);
    }
    asm volatile("cp.async.commit_group;");

    int r0 = rg * 16 + gid, r1 = r0 + 8;
    int kmax0 = (Q0 + r0) >> 2, kmax1 = (Q0 + r1) >> 2;
    int bt = Q0 >> 8;
    int n0 = half * 32;
    int cc = half * 64;

    float m0r = -1e30f, m1r = -1e30f;
    float sp0 = 0.f, sp1 = 0.f, sx0 = 0.f, sx1 = 0.f;
    float Om[8][4], Ox[8][4];
#pragma unroll
    for (int nf = 0; nf < 8; nf++)
#pragma unroll
        for (int j = 0; j < 4; j++) { Om[nf][j] = 0.f; Ox[nf][j] = 0.f; }

    const __half* Qr0 = Qs + r0 * QSTh;
    const __half* Qr1 = Qs + r1 * QSTh;

    for (int kt = 0; kt < 16; kt++) {
        __syncthreads();                                    // (A) shared K/V buf free
        // stage K tile: 64 rows x 16 granules
#pragma unroll
        for (int it = 0; it < 4; it++) {
            int f = it * 256 + tid;
            int r = f >> 4, g16 = f & 15;
            cpa16(sKV + (uint32_t)(r * (QSTh * 2) + g16 * 16),
                  Kb + (size_t)(kt * 64 + r) * HD + g16 * 8);
        }
        asm volatile("cp.async.commit_group;");
        asm volatile("cp.async.wait_group 0;");
        __syncthreads();                                    // (B)

        // S = Q K^T — fp16 mma, one LDS.64 per frag pair
        float c[4][4];
#pragma unroll
        for (int nf = 0; nf < 4; nf++)
#pragma unroll
            for (int j = 0; j < 4; j++) c[nf][j] = 0.f;
#pragma unroll
        for (int ks = 0; ks < 8; ks++) {
            int k0h = ks * 16 + tig * 4;
            uint2 qa = *(const uint2*)(Qr0 + k0h);
            uint2 qb = *(const uint2*)(Qr1 + k0h);
#pragma unroll
            for (int nf = 0; nf < 4; nf++) {
                uint2 kb2 = *(const uint2*)(Ks + (n0 + nf * 8 + gid) * QSTh + k0h);
                mma16h(c[nf], qa.x, qb.x, qa.y, qb.y, kb2.x, kb2.y);
            }
        }
        float t0 = -1e30f, t1 = -1e30f;
#pragma unroll
        for (int nf = 0; nf < 4; nf++) {
            t0 = fmaxf(t0, fmaxf(c[nf][0], c[nf][1]));
            t1 = fmaxf(t1, fmaxf(c[nf][2], c[nf][3]));
        }
        t0 = fmaxf(t0, __shfl_xor_sync(0xffffffffu, t0, 1));
        t0 = fmaxf(t0, __shfl_xor_sync(0xffffffffu, t0, 2));
        t1 = fmaxf(t1, __shfl_xor_sync(0xffffffffu, t1, 1));
        t1 = fmaxf(t1, __shfl_xor_sync(0xffffffffu, t1, 2));
        if (tig == 0) { wmx[half * 64 + r0] = t0; wmx[half * 64 + r1] = t1; }
        __syncthreads();                                    // (C) all K reads done

        // stage V2 tile: 32 kp rows x 32 granules (512B data per row)
#pragma unroll
        for (int it = 0; it < 4; it++) {
            int f = it * 256 + tid;
            int r = f >> 5, g32 = f & 31;
            cpa16(sKV + (uint32_t)(r * (V2ST * 4) + g32 * 16),
                  Vb + (size_t)(kt * 32 + r) * HD + g32 * 4);
        }
        asm volatile("cp.async.commit_group;");

        float mn0 = fmaxf(m0r, fmaxf(wmx[r0], wmx[64 + r0]));
        float mn1 = fmaxf(m1r, fmaxf(wmx[r1], wmx[64 + r1]));
        float sc0 = __expf(m0r - mn0);
        float sc1 = __expf(m1r - mn1);
        m0r = mn0; m1r = mn1;
        sp0 *= sc0; sx0 *= sc0; sp1 *= sc1; sx1 *= sc1;
#pragma unroll
        for (int nf = 0; nf < 8; nf++) {
            Om[nf][0] *= sc0; Om[nf][1] *= sc0; Om[nf][2] *= sc1; Om[nf][3] *= sc1;
            Ox[nf][0] *= sc0; Ox[nf][1] *= sc0; Ox[nf][2] *= sc1; Ox[nf][3] *= sc1;
        }
        float lp0 = 0.f, lx0 = 0.f, lp1 = 0.f, lx1 = 0.f;
#pragma unroll
        for (int nf = 0; nf < 4; nf++) {
            int kl = n0 + nf * 8 + 2 * tig;
            int kg = kt * 64 + kl;
            __half h0 = __float2half_rn(__expf(c[nf][0] - mn0));
            __half h1 = __float2half_rn(__expf(c[nf][1] - mn0));
            __half h2 = __float2half_rn(__expf(c[nf][2] - mn1));
            __half h3 = __float2half_rn(__expf(c[nf][3] - mn1));
            int blk = kl >> 4;
            int q   = (kl >> 1) & 7;
            int slot = (q < 4) ? 2 * q : 2 * q - 7;
            *(__half2*)(Ps + r0 * PSTh + blk * 16 + slot * 2) = __halves2half2(h0, h1);
            *(__half2*)(Ps + r1 * PSTh + blk * 16 + slot * 2) = __halves2half2(h2, h3);
            float p0 = __half2float(h0), p1 = __half2float(h1);
            float p2 = __half2float(h2), p3 = __half2float(h3);
            if (kg     <= kmax0) lp0 += p0; else lx0 += p0;
            if (kg + 1 <= kmax0) lp0 += p1; else lx0 += p1;
            if (kg     <= kmax1) lp1 += p2; else lx1 += p2;
            if (kg + 1 <= kmax1) lp1 += p3; else lx1 += p3;
        }
        lp0 += __shfl_xor_sync(0xffffffffu, lp0, 1); lp0 += __shfl_xor_sync(0xffffffffu, lp0, 2);
        lx0 += __shfl_xor_sync(0xffffffffu, lx0, 1); lx0 += __shfl_xor_sync(0xffffffffu, lx0, 2);
        lp1 += __shfl_xor_sync(0xffffffffu, lp1, 1); lp1 += __shfl_xor_sync(0xffffffffu, lp1, 2);
        lx1 += __shfl_xor_sync(0xffffffffu, lx1, 1); lx1 += __shfl_xor_sync(0xffffffffu, lx1, 2);
        if (tig == 0) {
            wsp[half * 64 + r0] = lp0; wsp[half * 64 + r1] = lp1;
            wsx[half * 64 + r0] = lx0; wsx[half * 64 + r1] = lx1;
        }
        asm volatile("cp.async.wait_group 0;");
        __syncthreads();                                    // (D) P, V2, sums ready

        sp0 += wsp[r0] + wsp[64 + r0];
        sp1 += wsp[r1] + wsp[64 + r1];
        sx0 += wsx[r0] + wsx[64 + r0];
        sx1 += wsx[r1] + wsx[64 + r1];

        const __half* Pr0 = Ps + r0 * PSTh;
        const __half* Pr1 = Ps + r1 * PSTh;
        if (kt < bt) {
#pragma unroll
            for (int ks = 0; ks < 4; ks++) {
                int k0h = ks * 16 + tig * 4;
                uint2 pa = *(const uint2*)(Pr0 + k0h);
                uint2 pb = *(const uint2*)(Pr1 + k0h);
#pragma unroll
                for (int nf = 0; nf < 8; nf++) {
                    int n = cc + nf * 8 + gid;
                    unsigned v0 = *(const unsigned*)(V2s + (ks * 8 + tig) * V2ST + n);
                    unsigned v1 = *(const unsigned*)(V2s + (ks * 8 + tig + 4) * V2ST + n);
                    mma16h(Om[nf], pa.x, pb.x, pa.y, pb.y, v0, v1);
                }
            }
        } else if (kt > bt) {
#pragma unroll
            for (int ks = 0; ks < 4; ks++) {
                int k0h = ks * 16 + tig * 4;
                uint2 pa = *(const uint2*)(Pr0 + k0h);
                uint2 pb = *(const uint2*)(Pr1 + k0h);
#pragma unroll
                for (int nf = 0; nf < 8; nf++) {
                    int n = cc + nf * 8 + gid;
                    unsigned v0 = *(const unsigned*)(V2s + (ks * 8 + tig) * V2ST + n);
                    unsigned v1 = *(const unsigned*)(V2s + (ks * 8 + tig + 4) * V2ST + n);
                    mma16h(Ox[nf], pa.x, pb.x, pa.y, pb.y, v0, v1);
                }
            }
        } else {
#pragma unroll
            for (int ks = 0; ks < 4; ks++) {
                int k0h = ks * 16 + tig * 4;
                uint2 pa = *(const uint2*)(Pr0 + k0h);
                uint2 pb = *(const uint2*)(Pr1 + k0h);
                int kb0 = kt * 64 + ks * 16 + 2 * tig;       // keys in low frag: kb0, kb0+1
                unsigned mA0 = ((kb0     <= kmax0) ? 0x0000FFFFu : 0u) |
                               ((kb0 + 1 <= kmax0) ? 0xFFFF0000u : 0u);
                unsigned mA2 = ((kb0 + 8 <= kmax0) ? 0x0000FFFFu : 0u) |
                               ((kb0 + 9 <= kmax0) ? 0xFFFF0000u : 0u);
                unsigned mB0 = ((kb0     <= kmax1) ? 0x0000FFFFu : 0u) |
                               ((kb0 + 1 <= kmax1) ? 0xFFFF0000u : 0u);
                unsigned mB2 = ((kb0 + 8 <= kmax1) ? 0x0000FFFFu : 0u) |
                               ((kb0 + 9 <= kmax1) ? 0xFFFF0000u : 0u);
                unsigned am0 = pa.x & mA0, am2 = pa.y & mA2;
                unsigned bm0 = pb.x & mB0, bm2 = pb.y & mB2;
                unsigned ax0 = pa.x & ~mA0, ax2 = pa.y & ~mA2;
                unsigned bx0 = pb.x & ~mB0, bx2 = pb.y & ~mB2;
#pragma unroll
                for (int nf = 0; nf < 8; nf++) {
                    int n = cc + nf * 8 + gid;
                    unsigned v0 = *(const unsigned*)(V2s + (ks * 8 + tig) * V2ST + n);
                    unsigned v1 = *(const unsigned*)(V2s + (ks * 8 + tig + 4) * V2ST + n);
                    mma16h(Om[nf], am0, bm0, am2, bm2, v0, v1);
                    mma16h(Ox[nf], ax0, bx0, ax2, bx2, v0, v1);
                }
            }
        }
    }

    // epilogue: atomic adds into zeroed Out
    float alpha = 1.f / (1.f + __expf(-__ldg(alpha_p)));
    float wp0 = alpha / sp0;
    float wp1 = alpha / sp1;
    float wu0 = (1.f - alpha) / (sp0 + sx0);
    float wu1 = (1.f - alpha) / (sp1 + sx1);

    int qg0 = Q0 + r0, qg1 = Q0 + r1;
    float* O0 = Out + ((size_t)b * T_ + qg0) * HD;
    float* O1 = Out + ((size_t)b * T_ + qg1) * HD;
    float* U0 = Out + ((size_t)b * T_ + (T_ - 1 - qg0)) * HD;
    float* U1 = Out + ((size_t)b * T_ + (T_ - 1 - qg1)) * HD;
#pragma unroll
    for (int nf = 0; nf < 8; nf++) {
        int col = cc + nf * 8 + 2 * tig;
        atomicAdd(O0 + col,     Om[nf][0] * wp0);
        atomicAdd(O0 + col + 1, Om[nf][1] * wp0);
        atomicAdd(O1 + col,     Om[nf][2] * wp1);
        atomicAdd(O1 + col + 1, Om[nf][3] * wp1);
        atomicAdd(U0 + col,     (Om[nf][0] + Ox[nf][0]) * wu0);
        atomicAdd(U0 + col + 1, (Om[nf][1] + Ox[nf][1]) * wu0);
        atomicAdd(U1 + col,     (Om[nf][2] + Ox[nf][2]) * wu1);
        atomicAdd(U1 + col + 1, (Om[nf][3] + Ox[nf][3]) * wu1);
    }
}

// ---------------- launch ----------------
extern "C" void kernel_launch(void* const* d_in, const int* in_sizes, int n_in,
                              void* d_out, int out_size) {
    const float* x  = (const float*)d_in[0];
    const float* Wq = (const float*)d_in[1];
    const float* Wk = (const float*)d_in[2];
    const float* Wv = (const float*)d_in[3];
    const float* fa = (const float*)d_in[9];
    float* out = (float*)d_out;

    const int PROJ_SMEM = (2 * ABUF + 2 * BBUF) * 4;                            // 69632 B
    const int ATTN_SMEM = 384 * 4 + (64 * QSTh * 2 + 64 * PSTh) * 2;            // 48128 B
    cudaFuncSetAttribute(proj_k, cudaFuncAttributeMaxDynamicSharedMemorySize, PROJ_SMEM);
    cudaFuncSetAttribute(attn_k, cudaFuncAttributeMaxDynamicSharedMemorySize, ATTN_SMEM);

    theta_k<<<1, 64>>>();
    rope_table_k<<<T_, 64>>>();
    cvtW_k<<<192, 256>>>(Wq, Wk, Wv);
    pool_x_k<<<(B_ * TKP * 128) / 256, 256>>>(x);
    proj_k<<<192, 256, PROJ_SMEM>>>(x);
    ropeh_k<<<(B_ * T_ * 4) / 256, 256>>>(0);
    ropeh_k<<<(B_ * TKP * 4) / 256, 256>>>(1);
    vpack_k<<<(B_ * 512 * 8) / 256, 256>>>();
    zero_k<<<(B_ * T_ * HD / 4) / 256, 256>>>(out);
    attn_k<<<dim3(T_ / 64, B_), 256, ATTN_SMEM>>>(fa, out);
}

// round 16
// speedup vs baseline: 1.1630x; 1.0105x over previous
#include <cuda_runtime.h>
#include <cuda_fp16.h>
#include <cstdint>

#define B_  4
#define T_  4096
#define TKP 1024
#define DM  1024
#define HD  128
#define SCALE_INV 0.08838834764831845f   // 1/sqrt(128)

// ---------------- static device scratch ----------------
__device__ float  g_xp[B_ * TKP * DM];
__device__ float  g_Q [B_ * T_  * HD];
__device__ float  g_K [B_ * TKP * HD];
__device__ float  g_V [B_ * TKP * HD];
__device__ float  g_Wt[3 * DM * HD];
__device__ __half g_Qh[B_ * T_  * HD];   // roped+scaled fp16, pair-interleaved per 16-block
__device__ __half g_Kh[B_ * TKP * HD];   // roped fp16, pair-interleaved per 16-block
__device__ __half2 g_V2[B_ * (TKP / 2) * HD];  // [b][key-pair][d] packed half2
__device__ float  g_cos[T_ * 64];
__device__ float  g_sin[T_ * 64];
__device__ double g_theta[64];

// ---------------- helpers ----------------
__device__ __forceinline__ unsigned f2t(float x) {
    unsigned r; asm("cvt.rna.tf32.f32 %0, %1;" : "=r"(r) : "f"(x)); return r;
}
__device__ __forceinline__ float f2tf(float x) { return __uint_as_float(f2t(x)); }
__device__ __forceinline__ float4 f2tf4(float4 v) {
    return make_float4(f2tf(v.x), f2tf(v.y), f2tf(v.z), f2tf(v.w));
}
__device__ __forceinline__ void mma8(float* d,
                                     float a0, float a1, float a2, float a3,
                                     float b0, float b1) {
    asm volatile("mma.sync.aligned.m16n8k8.row.col.f32.tf32.tf32.f32 "
                 "{%0,%1,%2,%3},{%4,%5,%6,%7},{%8,%9},{%0,%1,%2,%3};"
                 : "+f"(d[0]), "+f"(d[1]), "+f"(d[2]), "+f"(d[3])
                 : "r"(__float_as_uint(a0)), "r"(__float_as_uint(a1)),
                   "r"(__float_as_uint(a2)), "r"(__float_as_uint(a3)),
                   "r"(__float_as_uint(b0)), "r"(__float_as_uint(b1)));
}
__device__ __forceinline__ void mma16h(float* d,
                                       unsigned a0, unsigned a1, unsigned a2, unsigned a3,
                                       unsigned b0, unsigned b1) {
    asm volatile("mma.sync.aligned.m16n8k16.row.col.f32.f16.f16.f32 "
                 "{%0,%1,%2,%3},{%4,%5,%6,%7},{%8,%9},{%0,%1,%2,%3};"
                 : "+f"(d[0]), "+f"(d[1]), "+f"(d[2]), "+f"(d[3])
                 : "r"(a0), "r"(a1), "r"(a2), "r"(a3), "r"(b0), "r"(b1));
}
__device__ __forceinline__ void cpa16(uint32_t dst, const void* src) {
    asm volatile("cp.async.cg.shared.global [%0], [%1], 16;" :: "r"(dst), "l"(src));
}

// ---------------- RoPE tables ----------------
__global__ void theta_k() {
    int i = threadIdx.x;
    g_theta[i] = exp(((double)(-i) / 64.0) * log(10000.0));
}
__global__ void rope_table_k() {
    int t = blockIdx.x, i = threadIdx.x;
    float thf = (float)g_theta[i];
    float arg = (float)t * thf;
    const double TWO_PI  = 6.283185307179586476925286766559;
    const double INV2PI  = 0.15915494309189533576888376337251;
    double da = (double)arg;
    double k  = rint(da * INV2PI);
    float  r  = (float)(da - k * TWO_PI);
    g_cos[t * 64 + i] = cosf(r);
    g_sin[t * 64 + i] = sinf(r);
}

// ---------------- weights -> tf32 interleaved ----------------
__global__ void cvtW_k(const float* __restrict__ Wq, const float* __restrict__ Wk,
                       const float* __restrict__ Wv) {
    int g = blockIdx.x * 256 + threadIdx.x;
    int n = g & 127;
    int kb = (g >> 7) & 127;
    int which = g >> 14;
    const float* W = (which == 0) ? Wq : (which == 1 ? Wk : Wv);
    float w[8];
#pragma unroll
    for (int j = 0; j < 8; j++) w[j] = f2tf(W[(size_t)(kb * 8 + j) * HD + n]);
    float* dst = g_Wt + (((size_t)which * 128 + kb) * 128 + n) * 8;
    *(float4*)(dst)     = make_float4(w[0], w[4], w[1], w[5]);
    *(float4*)(dst + 4) = make_float4(w[2], w[6], w[3], w[7]);
}

// ---------------- stride-4 mean pool ----------------
__global__ void pool_x_k(const float* __restrict__ x) {
    int g  = blockIdx.x * 256 + threadIdx.x;
    int d8 = g & 127;
    int row = g >> 7;
    int b   = row >> 10, tp = row & 1023;
    const float* base = x + ((size_t)b * T_ + 4 * tp) * DM + d8 * 8;
    float v[8] = {0.f, 0.f, 0.f, 0.f, 0.f, 0.f, 0.f, 0.f};
#pragma unroll
    for (int r = 0; r < 4; r++) {
        float4 a = *(const float4*)(base + (size_t)r * DM);
        float4 c = *(const float4*)(base + (size_t)r * DM + 4);
        v[0] += a.x; v[1] += a.y; v[2] += a.z; v[3] += a.w;
        v[4] += c.x; v[5] += c.y; v[6] += c.z; v[7] += c.w;
    }
#pragma unroll
    for (int j = 0; j < 8; j++) v[j] = f2tf(v[j] * 0.25f);
    float* dst = g_xp + (size_t)row * DM + d8 * 8;
    *(float4*)(dst)     = make_float4(v[0], v[4], v[1], v[5]);
    *(float4*)(dst + 4) = make_float4(v[2], v[6], v[3], v[7]);
}

// ---------------- projection GEMM (R7/R13-proven) ----------------
#define AST 36
#define ABUF (128 * AST)
#define BBUF 4096
__global__ void __launch_bounds__(256, 2) proj_k(const float* __restrict__ x) {
    extern __shared__ __align__(16) float psm[];
    float* As = psm;
    float* Bs = psm + 2 * ABUF;

    int bid = blockIdx.x;
    const float* A; const float* Wm; float* Cm; int m0;
    bool isQ = false;
    if (bid < 128)      { A = x;    Wm = g_Wt;                Cm = g_Q; m0 = bid * 128; isQ = true; }
    else if (bid < 160) { A = g_xp; Wm = g_Wt + DM * HD;      Cm = g_K; m0 = (bid - 128) * 128; }
    else                { A = g_xp; Wm = g_Wt + 2 * DM * HD;  Cm = g_V; m0 = (bid - 160) * 128; }

    int tid  = threadIdx.x;
    int lane = tid & 31, wid = tid >> 5;
    int gid  = lane >> 2, tig = lane & 3;
    int wm = wid >> 1, wn = wid & 1;

    uint32_t sA = (uint32_t)__cvta_generic_to_shared(As);
    uint32_t sB = (uint32_t)__cvta_generic_to_shared(Bs);
    int ar = tid >> 3, ac = tid & 7;

    auto stage = [&](int kb, int buf) {
#pragma unroll
        for (int it = 0; it < 4; it++) {
            int r = ar + it * 32;
            cpa16(sA + (uint32_t)((buf * ABUF + r * AST + ac * 4) * 4),
                  A + (size_t)(m0 + r) * DM + kb * 32 + ac * 4);
        }
#pragma unroll
        for (int it = 0; it < 4; it++) {
            int idx = it * 256 + tid;
            cpa16(sB + (uint32_t)((buf * BBUF + idx * 4) * 4),
                  Wm + (size_t)kb * 4096 + idx * 4);
        }
        asm volatile("cp.async.commit_group;");
    };

    float C[2][8][4];
#pragma unroll
    for (int mf = 0; mf < 2; mf++)
#pragma unroll
        for (int nf = 0; nf < 8; nf++)
#pragma unroll
            for (int j = 0; j < 4; j++) C[mf][nf][j] = 0.f;

    stage(0, 0);
    stage(1, 1);

    for (int kb = 0; kb < 32; kb++) {
        if (kb < 30) { asm volatile("cp.async.wait_group 1;"); }
        else         { asm volatile("cp.async.wait_group 0;"); }
        __syncthreads();
        const float* Ab = As + (kb & 1) * ABUF;
        const float* Bb = Bs + (kb & 1) * BBUF;
#pragma unroll
        for (int ks = 0; ks < 4; ks++) {
            int k0 = ks * 8;
            float ah[2][4];
            if (isQ) {
#pragma unroll
                for (int mf = 0; mf < 2; mf++) {
                    int mb = wm * 32 + mf * 16;
                    ah[mf][0] = f2tf(Ab[(mb + gid)     * AST + k0 + tig]);
                    ah[mf][1] = f2tf(Ab[(mb + gid + 8) * AST + k0 + tig]);
                    ah[mf][2] = f2tf(Ab[(mb + gid)     * AST + k0 + tig + 4]);
                    ah[mf][3] = f2tf(Ab[(mb + gid + 8) * AST + k0 + tig + 4]);
                }
            } else {
#pragma unroll
                for (int mf = 0; mf < 2; mf++) {
                    int mb = wm * 32 + mf * 16;
                    float2 a0 = *(const float2*)(Ab + (mb + gid)     * AST + k0 + 2 * tig);
                    float2 a1 = *(const float2*)(Ab + (mb + gid + 8) * AST + k0 + 2 * tig);
                    ah[mf][0] = a0.x; ah[mf][1] = a1.x; ah[mf][2] = a0.y; ah[mf][3] = a1.y;
                }
            }
#pragma unroll
            for (int nf = 0; nf < 8; nf++) {
                int nb = wn * 64 + nf * 8 + gid;
                float2 bb = *(const float2*)(Bb + (ks * 128 + nb) * 8 + 2 * tig);
#pragma unroll
                for (int mf = 0; mf < 2; mf++)
                    mma8(C[mf][nf], ah[mf][0], ah[mf][1], ah[mf][2], ah[mf][3], bb.x, bb.y);
            }
        }
        __syncthreads();
        if (kb + 2 < 32) stage(kb + 2, kb & 1);
    }

#pragma unroll
    for (int mf = 0; mf < 2; mf++) {
        int r0 = m0 + wm * 32 + mf * 16 + gid;
#pragma unroll
        for (int nf = 0; nf < 8; nf++) {
            int col = wn * 64 + nf * 8 + 2 * tig;
            *(float2*)(Cm + (size_t)r0 * HD + col)       = make_float2(C[mf][nf][0], C[mf][nf][1]);
            *(float2*)(Cm + (size_t)(r0 + 8) * HD + col) = make_float2(C[mf][nf][2], C[mf][nf][3]);
        }
    }
}

// ---------------- RoPE -> fp16 pair-interleaved (R13-proven) ----------------
__global__ void ropeh_k(int which) {
    const float* X = which ? g_K : g_Q;
    __half* Xh     = which ? g_Kh : g_Qh;
    int mask   = which ? (TKP - 1) : (T_ - 1);
    float scl  = which ? 1.f : SCALE_INV;
    int g   = blockIdx.x * 256 + threadIdx.x;
    int blk = g & 3;
    int row = g >> 2;
    int pos = row & mask;
    float c[16], s[16], x1[16], x2[16];
    const float* cb = g_cos + pos * 64 + blk * 16;
    const float* sb = g_sin + pos * 64 + blk * 16;
#pragma unroll
    for (int q = 0; q < 4; q++) {
        *(float4*)(c + 4 * q) = *(const float4*)(cb + 4 * q);
        *(float4*)(s + 4 * q) = *(const float4*)(sb + 4 * q);
    }
    const float* p = X + (size_t)row * HD + blk * 16;
#pragma unroll
    for (int q = 0; q < 4; q++) {
        *(float4*)(x1 + 4 * q) = *(const float4*)(p + 4 * q);
        *(float4*)(x2 + 4 * q) = *(const float4*)(p + 64 + 4 * q);
    }
    float o1[16], o2[16];
#pragma unroll
    for (int j = 0; j < 16; j++) {
        o1[j] = (x1[j] * c[j] - x2[j] * s[j]) * scl;
        o2[j] = (x2[j] * c[j] + x1[j] * s[j]) * scl;
    }
    __half2 h1[8], h2[8];
#pragma unroll
    for (int t = 0; t < 4; t++) {
        h1[2 * t]     = __floats2half2_rn(o1[2 * t],     o1[2 * t + 1]);
        h1[2 * t + 1] = __floats2half2_rn(o1[2 * t + 8], o1[2 * t + 9]);
        h2[2 * t]     = __floats2half2_rn(o2[2 * t],     o2[2 * t + 1]);
        h2[2 * t + 1] = __floats2half2_rn(o2[2 * t + 8], o2[2 * t + 9]);
    }
    __half* dst = Xh + (size_t)row * HD + blk * 16;
    *(uint4*)(dst)      = *(uint4*)(h1);
    *(uint4*)(dst + 8)  = *(uint4*)(h1 + 4);
    *(uint4*)(dst + 64) = *(uint4*)(h2);
    *(uint4*)(dst + 72) = *(uint4*)(h2 + 4);
}

// ---------------- V -> key-pair-packed fp16 (R13-proven) ----------------
__global__ void vpack_k() {
    int g = blockIdx.x * 256 + threadIdx.x;
    int oct = g & 7;
    int kp  = g >> 3;
    const float* r0 = g_V + ((size_t)kp * 2) * HD + oct * 16;
    const float* r1 = r0 + HD;
    __half2 h[16];
#pragma unroll
    for (int q = 0; q < 4; q++) {
        float4 a = *(const float4*)(r0 + 4 * q);
        float4 b = *(const float4*)(r1 + 4 * q);
        h[4 * q + 0] = __floats2half2_rn(a.x, b.x);
        h[4 * q + 1] = __floats2half2_rn(a.y, b.y);
        h[4 * q + 2] = __floats2half2_rn(a.z, b.z);
        h[4 * q + 3] = __floats2half2_rn(a.w, b.w);
    }
    __half2* dst = g_V2 + (size_t)kp * HD + oct * 16;
    *(uint4*)(dst)      = *(uint4*)(h);
    *(uint4*)(dst + 4)  = *(uint4*)(h + 4);
    *(uint4*)(dst + 8)  = *(uint4*)(h + 8);
    *(uint4*)(dst + 12) = *(uint4*)(h + 12);
}

// ---------------- zero output ----------------
__global__ void zero_k(float* __restrict__ out) {
    ((float4*)out)[blockIdx.x * 256 + threadIdx.x] = make_float4(0.f, 0.f, 0.f, 0.f);
}

// ---------------- flash attention: 128 queries/CTA, 512 threads, fp16 datapath ----
#define QSTh 144     // halves per Q/K row
#define V2ST 136     // half2 per V2 row
#define PSTh 80      // halves per P row
__global__ void __launch_bounds__(512, 1) attn_k(const float* __restrict__ alpha_p,
                                                 float* __restrict__ Out)
{
    extern __shared__ __align__(16) float sm[];
    float* wmx = sm;                         // [2][128]
    float* wsp = wmx + 256;
    float* wsx = wsp + 256;
    __half* Qs = (__half*)(sm + 768);        // 128 x 144 halves
    __half* Ks = Qs + 128 * QSTh;            // 64 x 144 halves (shared with V2 tile)
    __half2* V2s = (__half2*)Ks;             // 32 x 136 half2
    __half* Ps = Ks + 64 * QSTh;             // 128 x 80 halves

    int tid  = threadIdx.x;
    int lane = tid & 31, wid = tid >> 5;
    int gid  = lane >> 2, tig = lane & 3;
    int rg   = wid >> 1, half = wid & 1;     // rg 0..7, half 0..1
    int Q0 = blockIdx.x * 128;
    int b  = blockIdx.y;
    const __half* Qb = g_Qh + ((size_t)b * T_ + Q0) * HD;
    const __half* Kb = g_Kh + (size_t)b * TKP * HD;
    const __half2* Vb = g_V2 + (size_t)b * (TKP / 2) * HD;

    uint32_t sQ  = (uint32_t)__cvta_generic_to_shared(Qs);
    uint32_t sKV = (uint32_t)__cvta_generic_to_shared(Ks);

    // stage Q: 128 rows x 16 granules = 2048
#pragma unroll
    for (int it = 0; it < 4; it++) {
        int f = it * 512 + tid;
        int r = f >> 4, g16 = f & 15;
        cpa16(sQ + (uint32_t)(r * (QSTh * 2) + g16 * 16), Qb + (size_t)r * HD + g16 * 8);
    }
    asm volatile("cp.async.commit_group;");

    int r0 = rg * 16 + gid, r1 = r0 + 8;     // rows 0..127
    int kmax0 = (Q0 + r0) >> 2, kmax1 = (Q0 + r1) >> 2;
    int bt = Q0 >> 8;                        // single boundary tile
    int n0 = half * 32;
    int cc = half * 64;

    float m0r = -1e30f, m1r = -1e30f;
    float sp0 = 0.f, sp1 = 0.f, sx0 = 0.f, sx1 = 0.f;
    float Om[8][4], Ox[8][4];
#pragma unroll
    for (int nf = 0; nf < 8; nf++)
#pragma unroll
        for (int j = 0; j < 4; j++) { Om[nf][j] = 0.f; Ox[nf][j] = 0.f; }

    const __half* Qr0 = Qs + r0 * QSTh;
    const __half* Qr1 = Qs + r1 * QSTh;

    for (int kt = 0; kt < 16; kt++) {
        __syncthreads();                                    // (A)
        // stage K tile: 64 rows x 16 granules = 1024
#pragma unroll
        for (int it = 0; it < 2; it++) {
            int f = it * 512 + tid;
            int r = f >> 4, g16 = f & 15;
            cpa16(sKV + (uint32_t)(r * (QSTh * 2) + g16 * 16),
                  Kb + (size_t)(kt * 64 + r) * HD + g16 * 8);
        }
        asm volatile("cp.async.commit_group;");
        asm volatile("cp.async.wait_group 0;");
        __syncthreads();                                    // (B)

        // S = Q K^T — fp16 mma
        float c[4][4];
#pragma unroll
        for (int nf = 0; nf < 4; nf++)
#pragma unroll
            for (int j = 0; j < 4; j++) c[nf][j] = 0.f;
#pragma unroll
        for (int ks = 0; ks < 8; ks++) {
            int k0h = ks * 16 + tig * 4;
            uint2 qa = *(const uint2*)(Qr0 + k0h);
            uint2 qb = *(const uint2*)(Qr1 + k0h);
#pragma unroll
            for (int nf = 0; nf < 4; nf++) {
                uint2 kb2 = *(const uint2*)(Ks + (n0 + nf * 8 + gid) * QSTh + k0h);
                mma16h(c[nf], qa.x, qb.x, qa.y, qb.y, kb2.x, kb2.y);
            }
        }
        float t0 = -1e30f, t1 = -1e30f;
#pragma unroll
        for (int nf = 0; nf < 4; nf++) {
            t0 = fmaxf(t0, fmaxf(c[nf][0], c[nf][1]));
            t1 = fmaxf(t1, fmaxf(c[nf][2], c[nf][3]));
        }
        t0 = fmaxf(t0, __shfl_xor_sync(0xffffffffu, t0, 1));
        t0 = fmaxf(t0, __shfl_xor_sync(0xffffffffu, t0, 2));
        t1 = fmaxf(t1, __shfl_xor_sync(0xffffffffu, t1, 1));
        t1 = fmaxf(t1, __shfl_xor_sync(0xffffffffu, t1, 2));
        if (tig == 0) { wmx[half * 128 + r0] = t0; wmx[half * 128 + r1] = t1; }
        __syncthreads();                                    // (C)

        // stage V2 tile: 32 kp rows x 32 granules = 1024
#pragma unroll
        for (int it = 0; it < 2; it++) {
            int f = it * 512 + tid;
            int r = f >> 5, g32 = f & 31;
            cpa16(sKV + (uint32_t)(r * (V2ST * 4) + g32 * 16),
                  Vb + (size_t)(kt * 32 + r) * HD + g32 * 4);
        }
        asm volatile("cp.async.commit_group;");

        float mn0 = fmaxf(m0r, fmaxf(wmx[r0], wmx[128 + r0]));
        float mn1 = fmaxf(m1r, fmaxf(wmx[r1], wmx[128 + r1]));
        float sc0 = __expf(m0r - mn0);
        float sc1 = __expf(m1r - mn1);
        m0r = mn0; m1r = mn1;
        sp0 *= sc0; sx0 *= sc0; sp1 *= sc1; sx1 *= sc1;
#pragma unroll
        for (int nf = 0; nf < 8; nf++) {
            Om[nf][0] *= sc0; Om[nf][1] *= sc0; Om[nf][2] *= sc1; Om[nf][3] *= sc1;
            Ox[nf][0] *= sc0; Ox[nf][1] *= sc0; Ox[nf][2] *= sc1; Ox[nf][3] *= sc1;
        }
        float lp0 = 0.f, lx0 = 0.f, lp1 = 0.f, lx1 = 0.f;
#pragma unroll
        for (int nf = 0; nf < 4; nf++) {
            int kl = n0 + nf * 8 + 2 * tig;
            int kg = kt * 64 + kl;
            __half h0 = __float2half_rn(__expf(c[nf][0] - mn0));
            __half h1 = __float2half_rn(__expf(c[nf][1] - mn0));
            __half h2 = __float2half_rn(__expf(c[nf][2] - mn1));
            __half h3 = __float2half_rn(__expf(c[nf][3] - mn1));
            int blk = kl >> 4;
            int q   = (kl >> 1) & 7;
            int slot = (q < 4) ? 2 * q : 2 * q - 7;
            *(__half2*)(Ps + r0 * PSTh + blk * 16 + slot * 2) = __halves2half2(h0, h1);
            *(__half2*)(Ps + r1 * PSTh + blk * 16 + slot * 2) = __halves2half2(h2, h3);
            float p0 = __half2float(h0), p1 = __half2float(h1);
            float p2 = __half2float(h2), p3 = __half2float(h3);
            if (kg     <= kmax0) lp0 += p0; else lx0 += p0;
            if (kg + 1 <= kmax0) lp0 += p1; else lx0 += p1;
            if (kg     <= kmax1) lp1 += p2; else lx1 += p2;
            if (kg + 1 <= kmax1) lp1 += p3; else lx1 += p3;
        }
        lp0 += __shfl_xor_sync(0xffffffffu, lp0, 1); lp0 += __shfl_xor_sync(0xffffffffu, lp0, 2);
        lx0 += __shfl_xor_sync(0xffffffffu, lx0, 1); lx0 += __shfl_xor_sync(0xffffffffu, lx0, 2);
        lp1 += __shfl_xor_sync(0xffffffffu, lp1, 1); lp1 += __shfl_xor_sync(0xffffffffu, lp1, 2);
        lx1 += __shfl_xor_sync(0xffffffffu, lx1, 1); lx1 += __shfl_xor_sync(0xffffffffu, lx1, 2);
        if (tig == 0) {
            wsp[half * 128 + r0] = lp0; wsp[half * 128 + r1] = lp1;
            wsx[half * 128 + r0] = lx0; wsx[half * 128 + r1] = lx1;
        }
        asm volatile("cp.async.wait_group 0;");
        __syncthreads();                                    // (D)

        sp0 += wsp[r0] + wsp[128 + r0];
        sp1 += wsp[r1] + wsp[128 + r1];
        sx0 += wsx[r0] + wsx[128 + r0];
        sx1 += wsx[r1] + wsx[128 + r1];

        const __half* Pr0 = Ps + r0 * PSTh;
        const __half* Pr1 = Ps + r1 * PSTh;
        if (kt < bt) {
#pragma unroll
            for (int ks = 0; ks < 4; ks++) {
                int k0h = ks * 16 + tig * 4;
                uint2 pa = *(const uint2*)(Pr0 + k0h);
                uint2 pb = *(const uint2*)(Pr1 + k0h);
#pragma unroll
                for (int nf = 0; nf < 8; nf++) {
                    int n = cc + nf * 8 + gid;
                    unsigned v0 = *(const unsigned*)(V2s + (ks * 8 + tig) * V2ST + n);
                    unsigned v1 = *(const unsigned*)(V2s + (ks * 8 + tig + 4) * V2ST + n);
                    mma16h(Om[nf], pa.x, pb.x, pa.y, pb.y, v0, v1);
                }
            }
        } else if (kt > bt) {
#pragma unroll
            for (int ks = 0; ks < 4; ks++) {
                int k0h = ks * 16 + tig * 4;
                uint2 pa = *(const uint2*)(Pr0 + k0h);
                uint2 pb = *(const uint2*)(Pr1 + k0h);
#pragma unroll
                for (int nf = 0; nf < 8; nf++) {
                    int n = cc + nf * 8 + gid;
                    unsigned v0 = *(const unsigned*)(V2s + (ks * 8 + tig) * V2ST + n);
                    unsigned v1 = *(const unsigned*)(V2s + (ks * 8 + tig + 4) * V2ST + n);
                    mma16h(Ox[nf], pa.x, pb.x, pa.y, pb.y, v0, v1);
                }
            }
        } else {
#pragma unroll
            for (int ks = 0; ks < 4; ks++) {
                int k0h = ks * 16 + tig * 4;
                uint2 pa = *(const uint2*)(Pr0 + k0h);
                uint2 pb = *(const uint2*)(Pr1 + k0h);
                int kb0 = kt * 64 + ks * 16 + 2 * tig;
                unsigned mA0 = ((kb0     <= kmax0) ? 0x0000FFFFu : 0u) |
                               ((kb0 + 1 <= kmax0) ? 0xFFFF0000u : 0u);
                unsigned mA2 = ((kb0 + 8 <= kmax0) ? 0x0000FFFFu : 0u) |
                               ((kb0 + 9 <= kmax0) ? 0xFFFF0000u : 0u);
                unsigned mB0 = ((kb0     <= kmax1) ? 0x0000FFFFu : 0u) |
                               ((kb0 + 1 <= kmax1) ? 0xFFFF0000u : 0u);
                unsigned mB2 = ((kb0 + 8 <= kmax1) ? 0x0000FFFFu : 0u) |
                               ((kb0 + 9 <= kmax1) ? 0xFFFF0000u : 0u);
                unsigned am0 = pa.x & mA0, am2 = pa.y & mA2;
                unsigned bm0 = pb.x & mB0, bm2 = pb.y & mB2;
                unsigned ax0 = pa.x & ~mA0, ax2 = pa.y & ~mA2;
                unsigned bx0 = pb.x & ~mB0, bx2 = pb.y & ~mB2;
#pragma unroll
                for (int nf = 0; nf < 8; nf++) {
                    int n = cc + nf * 8 + gid;
                    unsigned v0 = *(const unsigned*)(V2s + (ks * 8 + tig) * V2ST + n);
                    unsigned v1 = *(const unsigned*)(V2s + (ks * 8 + tig + 4) * V2ST + n);
                    mma16h(Om[nf], am0, bm0, am2, bm2, v0, v1);
                    mma16h(Ox[nf], ax0, bx0, ax2, bx2, v0, v1);
                }
            }
        }
    }

    // epilogue: atomic adds into zeroed Out
    float alpha = 1.f / (1.f + __expf(-__ldg(alpha_p)));
    float wp0 = alpha / sp0;
    float wp1 = alpha / sp1;
    float wu0 = (1.f - alpha) / (sp0 + sx0);
    float wu1 = (1.f - alpha) / (sp1 + sx1);

    int qg0 = Q0 + r0, qg1 = Q0 + r1;
    float* O0 = Out + ((size_t)b * T_ + qg0) * HD;
    float* O1 = Out + ((size_t)b * T_ + qg1) * HD;
    float* U0 = Out + ((size_t)b * T_ + (T_ - 1 - qg0)) * HD;
    float* U1 = Out + ((size_t)b * T_ + (T_ - 1 - qg1)) * HD;
#pragma unroll
    for (int nf = 0; nf < 8; nf++) {
        int col = cc + nf * 8 + 2 * tig;
        atomicAdd(O0 + col,     Om[nf][0] * wp0);
        atomicAdd(O0 + col + 1, Om[nf][1] * wp0);
        atomicAdd(O1 + col,     Om[nf][2] * wp1);
        atomicAdd(O1 + col + 1, Om[nf][3] * wp1);
        atomicAdd(U0 + col,     (Om[nf][0] + Ox[nf][0]) * wu0);
        atomicAdd(U0 + col + 1, (Om[nf][1] + Ox[nf][1]) * wu0);
        atomicAdd(U1 + col,     (Om[nf][2] + Ox[nf][2]) * wu1);
        atomicAdd(U1 + col + 1, (Om[nf][3] + Ox[nf][3]) * wu1);
    }
}

// ---------------- launch ----------------
extern "C" void kernel_launch(void* const* d_in, const int* in_sizes, int n_in,
                              void* d_out, int out_size) {
    const float* x  = (const float*)d_in[0];
    const float* Wq = (const float*)d_in[1];
    const float* Wk = (const float*)d_in[2];
    const float* Wv = (const float*)d_in[3];
    const float* fa = (const float*)d_in[9];
    float* out = (float*)d_out;

    const int PROJ_SMEM = (2 * ABUF + 2 * BBUF) * 4;                            // 69632 B
    const int ATTN_SMEM = 768 * 4 + (128 * QSTh + 64 * QSTh) * 2 + 128 * PSTh * 2;  // 78848 B
    cudaFuncSetAttribute(proj_k, cudaFuncAttributeMaxDynamicSharedMemorySize, PROJ_SMEM);
    cudaFuncSetAttribute(attn_k, cudaFuncAttributeMaxDynamicSharedMemorySize, ATTN_SMEM);

    theta_k<<<1, 64>>>();
    rope_table_k<<<T_, 64>>>();
    cvtW_k<<<192, 256>>>(Wq, Wk, Wv);
    pool_x_k<<<(B_ * TKP * 128) / 256, 256>>>(x);
    proj_k<<<192, 256, PROJ_SMEM>>>(x);
    ropeh_k<<<(B_ * T_ * 4) / 256, 256>>>(0);
    ropeh_k<<<(B_ * TKP * 4) / 256, 256>>>(1);
    vpack_k<<<(B_ * 512 * 8) / 256, 256>>>();
    zero_k<<<(B_ * T_ * HD / 4) / 256, 256>>>(out);
    attn_k<<<dim3(T_ / 128, B_), 512, ATTN_SMEM>>>(fa, out);
}

// round 17
// speedup vs baseline: 1.1910x; 1.0241x over previous
#include <cuda_runtime.h>
#include <cuda_fp16.h>
#include <cstdint>

#define B_  4
#define T_  4096
#define TKP 1024
#define DM  1024
#define HD  128
#define SCALE_INV 0.08838834764831845f   // 1/sqrt(128)

// ---------------- static device scratch ----------------
__device__ float  g_xp[B_ * TKP * DM];
__device__ float  g_Q [B_ * T_  * HD];
__device__ float  g_K [B_ * TKP * HD];
__device__ float  g_V [B_ * TKP * HD];
__device__ float  g_Wt[3 * DM * HD];
__device__ __half g_Qh[B_ * T_  * HD];   // roped+scaled fp16, pair-interleaved per 16-block
__device__ __half g_Kh[B_ * TKP * HD];   // roped fp16, pair-interleaved per 16-block
__device__ __half2 g_V2[B_ * (TKP / 2) * HD];  // [b][key-pair][d] packed half2
__device__ float  g_cos[T_ * 64];
__device__ float  g_sin[T_ * 64];
__device__ double g_theta[64];

// ---------------- helpers ----------------
__device__ __forceinline__ unsigned f2t(float x) {
    unsigned r; asm("cvt.rna.tf32.f32 %0, %1;" : "=r"(r) : "f"(x)); return r;
}
__device__ __forceinline__ float f2tf(float x) { return __uint_as_float(f2t(x)); }
__device__ __forceinline__ float4 f2tf4(float4 v) {
    return make_float4(f2tf(v.x), f2tf(v.y), f2tf(v.z), f2tf(v.w));
}
__device__ __forceinline__ void mma8(float* d,
                                     float a0, float a1, float a2, float a3,
                                     float b0, float b1) {
    asm volatile("mma.sync.aligned.m16n8k8.row.col.f32.tf32.tf32.f32 "
                 "{%0,%1,%2,%3},{%4,%5,%6,%7},{%8,%9},{%0,%1,%2,%3};"
                 : "+f"(d[0]), "+f"(d[1]), "+f"(d[2]), "+f"(d[3])
                 : "r"(__float_as_uint(a0)), "r"(__float_as_uint(a1)),
                   "r"(__float_as_uint(a2)), "r"(__float_as_uint(a3)),
                   "r"(__float_as_uint(b0)), "r"(__float_as_uint(b1)));
}
__device__ __forceinline__ void mma16h(float* d,
                                       unsigned a0, unsigned a1, unsigned a2, unsigned a3,
                                       unsigned b0, unsigned b1) {
    asm volatile("mma.sync.aligned.m16n8k16.row.col.f32.f16.f16.f32 "
                 "{%0,%1,%2,%3},{%4,%5,%6,%7},{%8,%9},{%0,%1,%2,%3};"
                 : "+f"(d[0]), "+f"(d[1]), "+f"(d[2]), "+f"(d[3])
                 : "r"(a0), "r"(a1), "r"(a2), "r"(a3), "r"(b0), "r"(b1));
}
__device__ __forceinline__ void cpa16(uint32_t dst, const void* src) {
    asm volatile("cp.async.cg.shared.global [%0], [%1], 16;" :: "r"(dst), "l"(src));
}

// ---------------- RoPE tables ----------------
__global__ void theta_k() {
    int i = threadIdx.x;
    g_theta[i] = exp(((double)(-i) / 64.0) * log(10000.0));
}
__global__ void rope_table_k() {
    int t = blockIdx.x, i = threadIdx.x;
    float thf = (float)g_theta[i];
    float arg = (float)t * thf;
    const double TWO_PI  = 6.283185307179586476925286766559;
    const double INV2PI  = 0.15915494309189533576888376337251;
    double da = (double)arg;
    double k  = rint(da * INV2PI);
    float  r  = (float)(da - k * TWO_PI);
    g_cos[t * 64 + i] = cosf(r);
    g_sin[t * 64 + i] = sinf(r);
}

// ---------------- weights -> tf32 interleaved ----------------
__global__ void cvtW_k(const float* __restrict__ Wq, const float* __restrict__ Wk,
                       const float* __restrict__ Wv) {
    int g = blockIdx.x * 256 + threadIdx.x;
    int n = g & 127;
    int kb = (g >> 7) & 127;
    int which = g >> 14;
    const float* W = (which == 0) ? Wq : (which == 1 ? Wk : Wv);
    float w[8];
#pragma unroll
    for (int j = 0; j < 8; j++) w[j] = f2tf(W[(size_t)(kb * 8 + j) * HD + n]);
    float* dst = g_Wt + (((size_t)which * 128 + kb) * 128 + n) * 8;
    *(float4*)(dst)     = make_float4(w[0], w[4], w[1], w[5]);
    *(float4*)(dst + 4) = make_float4(w[2], w[6], w[3], w[7]);
}

// ---------------- stride-4 mean pool ----------------
__global__ void pool_x_k(const float* __restrict__ x) {
    int g  = blockIdx.x * 256 + threadIdx.x;
    int d8 = g & 127;
    int row = g >> 7;
    int b   = row >> 10, tp = row & 1023;
    const float* base = x + ((size_t)b * T_ + 4 * tp) * DM + d8 * 8;
    float v[8] = {0.f, 0.f, 0.f, 0.f, 0.f, 0.f, 0.f, 0.f};
#pragma unroll
    for (int r = 0; r < 4; r++) {
        float4 a = *(const float4*)(base + (size_t)r * DM);
        float4 c = *(const float4*)(base + (size_t)r * DM + 4);
        v[0] += a.x; v[1] += a.y; v[2] += a.z; v[3] += a.w;
        v[4] += c.x; v[5] += c.y; v[6] += c.z; v[7] += c.w;
    }
#pragma unroll
    for (int j = 0; j < 8; j++) v[j] = f2tf(v[j] * 0.25f);
    float* dst = g_xp + (size_t)row * DM + d8 * 8;
    *(float4*)(dst)     = make_float4(v[0], v[4], v[1], v[5]);
    *(float4*)(dst + 4) = make_float4(v[2], v[6], v[3], v[7]);
}

// ---------------- projection GEMM (R7/R13-proven) ----------------
#define AST 36
#define ABUF (128 * AST)
#define BBUF 4096
__global__ void __launch_bounds__(256, 2) proj_k(const float* __restrict__ x) {
    extern __shared__ __align__(16) float psm[];
    float* As = psm;
    float* Bs = psm + 2 * ABUF;

    int bid = blockIdx.x;
    const float* A; const float* Wm; float* Cm; int m0;
    bool isQ = false;
    if (bid < 128)      { A = x;    Wm = g_Wt;                Cm = g_Q; m0 = bid * 128; isQ = true; }
    else if (bid < 160) { A = g_xp; Wm = g_Wt + DM * HD;      Cm = g_K; m0 = (bid - 128) * 128; }
    else                { A = g_xp; Wm = g_Wt + 2 * DM * HD;  Cm = g_V; m0 = (bid - 160) * 128; }

    int tid  = threadIdx.x;
    int lane = tid & 31, wid = tid >> 5;
    int gid  = lane >> 2, tig = lane & 3;
    int wm = wid >> 1, wn = wid & 1;

    uint32_t sA = (uint32_t)__cvta_generic_to_shared(As);
    uint32_t sB = (uint32_t)__cvta_generic_to_shared(Bs);
    int ar = tid >> 3, ac = tid & 7;

    auto stage = [&](int kb, int buf) {
#pragma unroll
        for (int it = 0; it < 4; it++) {
            int r = ar + it * 32;
            cpa16(sA + (uint32_t)((buf * ABUF + r * AST + ac * 4) * 4),
                  A + (size_t)(m0 + r) * DM + kb * 32 + ac * 4);
        }
#pragma unroll
        for (int it = 0; it < 4; it++) {
            int idx = it * 256 + tid;
            cpa16(sB + (uint32_t)((buf * BBUF + idx * 4) * 4),
                  Wm + (size_t)kb * 4096 + idx * 4);
        }
        asm volatile("cp.async.commit_group;");
    };

    float C[2][8][4];
#pragma unroll
    for (int mf = 0; mf < 2; mf++)
#pragma unroll
        for (int nf = 0; nf < 8; nf++)
#pragma unroll
            for (int j = 0; j < 4; j++) C[mf][nf][j] = 0.f;

    stage(0, 0);
    stage(1, 1);

    for (int kb = 0; kb < 32; kb++) {
        if (kb < 30) { asm volatile("cp.async.wait_group 1;"); }
        else         { asm volatile("cp.async.wait_group 0;"); }
        __syncthreads();
        const float* Ab = As + (kb & 1) * ABUF;
        const float* Bb = Bs + (kb & 1) * BBUF;
#pragma unroll
        for (int ks = 0; ks < 4; ks++) {
            int k0 = ks * 8;
            float ah[2][4];
            if (isQ) {
#pragma unroll
                for (int mf = 0; mf < 2; mf++) {
                    int mb = wm * 32 + mf * 16;
                    ah[mf][0] = f2tf(Ab[(mb + gid)     * AST + k0 + tig]);
                    ah[mf][1] = f2tf(Ab[(mb + gid + 8) * AST + k0 + tig]);
                    ah[mf][2] = f2tf(Ab[(mb + gid)     * AST + k0 + tig + 4]);
                    ah[mf][3] = f2tf(Ab[(mb + gid + 8) * AST + k0 + tig + 4]);
                }
            } else {
#pragma unroll
                for (int mf = 0; mf < 2; mf++) {
                    int mb = wm * 32 + mf * 16;
                    float2 a0 = *(const float2*)(Ab + (mb + gid)     * AST + k0 + 2 * tig);
                    float2 a1 = *(const float2*)(Ab + (mb + gid + 8) * AST + k0 + 2 * tig);
                    ah[mf][0] = a0.x; ah[mf][1] = a1.x; ah[mf][2] = a0.y; ah[mf][3] = a1.y;
                }
            }
#pragma unroll
            for (int nf = 0; nf < 8; nf++) {
                int nb = wn * 64 + nf * 8 + gid;
                float2 bb = *(const float2*)(Bb + (ks * 128 + nb) * 8 + 2 * tig);
#pragma unroll
                for (int mf = 0; mf < 2; mf++)
                    mma8(C[mf][nf], ah[mf][0], ah[mf][1], ah[mf][2], ah[mf][3], bb.x, bb.y);
            }
        }
        __syncthreads();
        if (kb + 2 < 32) stage(kb + 2, kb & 1);
    }

#pragma unroll
    for (int mf = 0; mf < 2; mf++) {
        int r0 = m0 + wm * 32 + mf * 16 + gid;
#pragma unroll
        for (int nf = 0; nf < 8; nf++) {
            int col = wn * 64 + nf * 8 + 2 * tig;
            *(float2*)(Cm + (size_t)r0 * HD + col)       = make_float2(C[mf][nf][0], C[mf][nf][1]);
            *(float2*)(Cm + (size_t)(r0 + 8) * HD + col) = make_float2(C[mf][nf][2], C[mf][nf][3]);
        }
    }
}

// ---------------- RoPE -> fp16 pair-interleaved (R13-proven) ----------------
__global__ void ropeh_k(int which) {
    const float* X = which ? g_K : g_Q;
    __half* Xh     = which ? g_Kh : g_Qh;
    int mask   = which ? (TKP - 1) : (T_ - 1);
    float scl  = which ? 1.f : SCALE_INV;
    int g   = blockIdx.x * 256 + threadIdx.x;
    int blk = g & 3;
    int row = g >> 2;
    int pos = row & mask;
    float c[16], s[16], x1[16], x2[16];
    const float* cb = g_cos + pos * 64 + blk * 16;
    const float* sb = g_sin + pos * 64 + blk * 16;
#pragma unroll
    for (int q = 0; q < 4; q++) {
        *(float4*)(c + 4 * q) = *(const float4*)(cb + 4 * q);
        *(float4*)(s + 4 * q) = *(const float4*)(sb + 4 * q);
    }
    const float* p = X + (size_t)row * HD + blk * 16;
#pragma unroll
    for (int q = 0; q < 4; q++) {
        *(float4*)(x1 + 4 * q) = *(const float4*)(p + 4 * q);
        *(float4*)(x2 + 4 * q) = *(const float4*)(p + 64 + 4 * q);
    }
    float o1[16], o2[16];
#pragma unroll
    for (int j = 0; j < 16; j++) {
        o1[j] = (x1[j] * c[j] - x2[j] * s[j]) * scl;
        o2[j] = (x2[j] * c[j] + x1[j] * s[j]) * scl;
    }
    __half2 h1[8], h2[8];
#pragma unroll
    for (int t = 0; t < 4; t++) {
        h1[2 * t]     = __floats2half2_rn(o1[2 * t],     o1[2 * t + 1]);
        h1[2 * t + 1] = __floats2half2_rn(o1[2 * t + 8], o1[2 * t + 9]);
        h2[2 * t]     = __floats2half2_rn(o2[2 * t],     o2[2 * t + 1]);
        h2[2 * t + 1] = __floats2half2_rn(o2[2 * t + 8], o2[2 * t + 9]);
    }
    __half* dst = Xh + (size_t)row * HD + blk * 16;
    *(uint4*)(dst)      = *(uint4*)(h1);
    *(uint4*)(dst + 8)  = *(uint4*)(h1 + 4);
    *(uint4*)(dst + 64) = *(uint4*)(h2);
    *(uint4*)(dst + 72) = *(uint4*)(h2 + 4);
}

// ---------------- V -> key-pair-packed fp16 (R13-proven) ----------------
__global__ void vpack_k() {
    int g = blockIdx.x * 256 + threadIdx.x;
    int oct = g & 7;
    int kp  = g >> 3;
    const float* r0 = g_V + ((size_t)kp * 2) * HD + oct * 16;
    const float* r1 = r0 + HD;
    __half2 h[16];
#pragma unroll
    for (int q = 0; q < 4; q++) {
        float4 a = *(const float4*)(r0 + 4 * q);
        float4 b = *(const float4*)(r1 + 4 * q);
        h[4 * q + 0] = __floats2half2_rn(a.x, b.x);
        h[4 * q + 1] = __floats2half2_rn(a.y, b.y);
        h[4 * q + 2] = __floats2half2_rn(a.z, b.z);
        h[4 * q + 3] = __floats2half2_rn(a.w, b.w);
    }
    __half2* dst = g_V2 + (size_t)kp * HD + oct * 16;
    *(uint4*)(dst)      = *(uint4*)(h);
    *(uint4*)(dst + 4)  = *(uint4*)(h + 4);
    *(uint4*)(dst + 8)  = *(uint4*)(h + 8);
    *(uint4*)(dst + 12) = *(uint4*)(h + 12);
}

// ---------------- zero output ----------------
__global__ void zero_k(float* __restrict__ out) {
    ((float4*)out)[blockIdx.x * 256 + threadIdx.x] = make_float4(0.f, 0.f, 0.f, 0.f);
}

// ---------------- flash attention: 128q/CTA, double-buffered K/V tile pipeline ----
#define QSTh 144     // halves per Q/K row
#define V2ST 136     // half2 per V2 row
#define PSTh 80      // halves per P row
__global__ void __launch_bounds__(512, 1) attn_k(const float* __restrict__ alpha_p,
                                                 float* __restrict__ Out)
{
    extern __shared__ __align__(16) float sm[];
    float* wmx = sm;                          // [2][128]
    float* wsp = wmx + 256;
    float* wsx = wsp + 256;
    __half* Qs   = (__half*)(sm + 768);       // 128 x 144
    __half* Kbuf = Qs + 128 * QSTh;           // 2 x (64 x 144)
    __half2* Vbuf = (__half2*)(Kbuf + 2 * 64 * QSTh);  // 2 x (32 x 136)
    __half* Ps   = (__half*)(Vbuf + 2 * 32 * V2ST);    // 128 x 80

    int tid  = threadIdx.x;
    int lane = tid & 31, wid = tid >> 5;
    int gid  = lane >> 2, tig = lane & 3;
    int rg   = wid >> 1, half = wid & 1;
    int Q0 = blockIdx.x * 128;
    int b  = blockIdx.y;
    const __half* Qb = g_Qh + ((size_t)b * T_ + Q0) * HD;
    const __half* Kb = g_Kh + (size_t)b * TKP * HD;
    const __half2* Vb = g_V2 + (size_t)b * (TKP / 2) * HD;

    uint32_t sQ = (uint32_t)__cvta_generic_to_shared(Qs);
    uint32_t sK = (uint32_t)__cvta_generic_to_shared(Kbuf);
    uint32_t sV = (uint32_t)__cvta_generic_to_shared(Vbuf);

    // stage tile t (K 64 rows + V 32 kp rows) into buffer bf; one commit group
    auto stage_tile = [&](int t, int bf) {
#pragma unroll
        for (int it = 0; it < 2; it++) {
            int f = it * 512 + tid;
            int r = f >> 4, g16 = f & 15;
            cpa16(sK + (uint32_t)((bf * 64 * QSTh + r * QSTh) * 2 + g16 * 16),
                  Kb + (size_t)(t * 64 + r) * HD + g16 * 8);
        }
#pragma unroll
        for (int it = 0; it < 2; it++) {
            int f = it * 512 + tid;
            int r = f >> 5, g32 = f & 31;
            cpa16(sV + (uint32_t)((bf * 32 * V2ST + r * V2ST) * 4 + g32 * 16),
                  Vb + (size_t)(t * 32 + r) * HD + g32 * 4);
        }
        asm volatile("cp.async.commit_group;");
    };

    // prolog: Q group, then tile 0 group
#pragma unroll
    for (int it = 0; it < 4; it++) {
        int f = it * 512 + tid;
        int r = f >> 4, g16 = f & 15;
        cpa16(sQ + (uint32_t)(r * (QSTh * 2) + g16 * 16), Qb + (size_t)r * HD + g16 * 8);
    }
    asm volatile("cp.async.commit_group;");
    stage_tile(0, 0);

    int r0 = rg * 16 + gid, r1 = r0 + 8;
    int kmax0 = (Q0 + r0) >> 2, kmax1 = (Q0 + r1) >> 2;
    int bt = Q0 >> 8;
    int n0 = half * 32;
    int cc = half * 64;

    float m0r = -1e30f, m1r = -1e30f;
    float sp0 = 0.f, sp1 = 0.f, sx0 = 0.f, sx1 = 0.f;
    float Om[8][4], Ox[8][4];
#pragma unroll
    for (int nf = 0; nf < 8; nf++)
#pragma unroll
        for (int j = 0; j < 4; j++) { Om[nf][j] = 0.f; Ox[nf][j] = 0.f; }

    const __half* Qr0 = Qs + r0 * QSTh;
    const __half* Qr1 = Qs + r1 * QSTh;

    for (int kt = 0; kt < 16; kt++) {
        int cur = kt & 1;
        __syncthreads();                        // (a) buffer (kt+1)&1 free: PV of kt-1 done
        if (kt < 15) {
            stage_tile(kt + 1, (kt + 1) & 1);
            asm volatile("cp.async.wait_group 1;");   // tile kt arrived (requested 1 iter ago)
        } else {
            asm volatile("cp.async.wait_group 0;");
        }
        __syncthreads();                        // (b) tile kt visible to all

        const __half* Kc = Kbuf + cur * 64 * QSTh;
        const __half2* V2c = Vbuf + cur * 32 * V2ST;

        // S = Q K^T — fp16 mma
        float c[4][4];
#pragma unroll
        for (int nf = 0; nf < 4; nf++)
#pragma unroll
            for (int j = 0; j < 4; j++) c[nf][j] = 0.f;
#pragma unroll
        for (int ks = 0; ks < 8; ks++) {
            int k0h = ks * 16 + tig * 4;
            uint2 qa = *(const uint2*)(Qr0 + k0h);
            uint2 qb = *(const uint2*)(Qr1 + k0h);
#pragma unroll
            for (int nf = 0; nf < 4; nf++) {
                uint2 kb2 = *(const uint2*)(Kc + (n0 + nf * 8 + gid) * QSTh + k0h);
                mma16h(c[nf], qa.x, qb.x, qa.y, qb.y, kb2.x, kb2.y);
            }
        }
        float t0 = -1e30f, t1 = -1e30f;
#pragma unroll
        for (int nf = 0; nf < 4; nf++) {
            t0 = fmaxf(t0, fmaxf(c[nf][0], c[nf][1]));
            t1 = fmaxf(t1, fmaxf(c[nf][2], c[nf][3]));
        }
        t0 = fmaxf(t0, __shfl_xor_sync(0xffffffffu, t0, 1));
        t0 = fmaxf(t0, __shfl_xor_sync(0xffffffffu, t0, 2));
        t1 = fmaxf(t1, __shfl_xor_sync(0xffffffffu, t1, 1));
        t1 = fmaxf(t1, __shfl_xor_sync(0xffffffffu, t1, 2));
        if (tig == 0) { wmx[half * 128 + r0] = t0; wmx[half * 128 + r1] = t1; }
        __syncthreads();                        // (C)

        float mn0 = fmaxf(m0r, fmaxf(wmx[r0], wmx[128 + r0]));
        float mn1 = fmaxf(m1r, fmaxf(wmx[r1], wmx[128 + r1]));
        float sc0 = __expf(m0r - mn0);
        float sc1 = __expf(m1r - mn1);
        m0r = mn0; m1r = mn1;
        sp0 *= sc0; sx0 *= sc0; sp1 *= sc1; sx1 *= sc1;
#pragma unroll
        for (int nf = 0; nf < 8; nf++) {
            Om[nf][0] *= sc0; Om[nf][1] *= sc0; Om[nf][2] *= sc1; Om[nf][3] *= sc1;
            Ox[nf][0] *= sc0; Ox[nf][1] *= sc0; Ox[nf][2] *= sc1; Ox[nf][3] *= sc1;
        }
        float lp0 = 0.f, lx0 = 0.f, lp1 = 0.f, lx1 = 0.f;
#pragma unroll
        for (int nf = 0; nf < 4; nf++) {
            int kl = n0 + nf * 8 + 2 * tig;
            int kg = kt * 64 + kl;
            __half h0 = __float2half_rn(__expf(c[nf][0] - mn0));
            __half h1 = __float2half_rn(__expf(c[nf][1] - mn0));
            __half h2 = __float2half_rn(__expf(c[nf][2] - mn1));
            __half h3 = __float2half_rn(__expf(c[nf][3] - mn1));
            int blk = kl >> 4;
            int q   = (kl >> 1) & 7;
            int slot = (q < 4) ? 2 * q : 2 * q - 7;
            *(__half2*)(Ps + r0 * PSTh + blk * 16 + slot * 2) = __halves2half2(h0, h1);
            *(__half2*)(Ps + r1 * PSTh + blk * 16 + slot * 2) = __halves2half2(h2, h3);
            float p0 = __half2float(h0), p1 = __half2float(h1);
            float p2 = __half2float(h2), p3 = __half2float(h3);
            if (kg     <= kmax0) lp0 += p0; else lx0 += p0;
            if (kg + 1 <= kmax0) lp0 += p1; else lx0 += p1;
            if (kg     <= kmax1) lp1 += p2; else lx1 += p2;
            if (kg + 1 <= kmax1) lp1 += p3; else lx1 += p3;
        }
        lp0 += __shfl_xor_sync(0xffffffffu, lp0, 1); lp0 += __shfl_xor_sync(0xffffffffu, lp0, 2);
        lx0 += __shfl_xor_sync(0xffffffffu, lx0, 1); lx0 += __shfl_xor_sync(0xffffffffu, lx0, 2);
        lp1 += __shfl_xor_sync(0xffffffffu, lp1, 1); lp1 += __shfl_xor_sync(0xffffffffu, lp1, 2);
        lx1 += __shfl_xor_sync(0xffffffffu, lx1, 1); lx1 += __shfl_xor_sync(0xffffffffu, lx1, 2);
        if (tig == 0) {
            wsp[half * 128 + r0] = lp0; wsp[half * 128 + r1] = lp1;
            wsx[half * 128 + r0] = lx0; wsx[half * 128 + r1] = lx1;
        }
        __syncthreads();                        // (D) P + sums ready

        sp0 += wsp[r0] + wsp[128 + r0];
        sp1 += wsp[r1] + wsp[128 + r1];
        sx0 += wsx[r0] + wsx[128 + r0];
        sx1 += wsx[r1] + wsx[128 + r1];

        const __half* Pr0 = Ps + r0 * PSTh;
        const __half* Pr1 = Ps + r1 * PSTh;
        if (kt < bt) {
#pragma unroll
            for (int ks = 0; ks < 4; ks++) {
                int k0h = ks * 16 + tig * 4;
                uint2 pa = *(const uint2*)(Pr0 + k0h);
                uint2 pb = *(const uint2*)(Pr1 + k0h);
#pragma unroll
                for (int nf = 0; nf < 8; nf++) {
                    int n = cc + nf * 8 + gid;
                    unsigned v0 = *(const unsigned*)(V2c + (ks * 8 + tig) * V2ST + n);
                    unsigned v1 = *(const unsigned*)(V2c + (ks * 8 + tig + 4) * V2ST + n);
                    mma16h(Om[nf], pa.x, pb.x, pa.y, pb.y, v0, v1);
                }
            }
        } else if (kt > bt) {
#pragma unroll
            for (int ks = 0; ks < 4; ks++) {
                int k0h = ks * 16 + tig * 4;
                uint2 pa = *(const uint2*)(Pr0 + k0h);
                uint2 pb = *(const uint2*)(Pr1 + k0h);
#pragma unroll
                for (int nf = 0; nf < 8; nf++) {
                    int n = cc + nf * 8 + gid;
                    unsigned v0 = *(const unsigned*)(V2c + (ks * 8 + tig) * V2ST + n);
                    unsigned v1 = *(const unsigned*)(V2c + (ks * 8 + tig + 4) * V2ST + n);
                    mma16h(Ox[nf], pa.x, pb.x, pa.y, pb.y, v0, v1);
                }
            }
        } else {
#pragma unroll
            for (int ks = 0; ks < 4; ks++) {
                int k0h = ks * 16 + tig * 4;
                uint2 pa = *(const uint2*)(Pr0 + k0h);
                uint2 pb = *(const uint2*)(Pr1 + k0h);
                int kb0 = kt * 64 + ks * 16 + 2 * tig;
                unsigned mA0 = ((kb0     <= kmax0) ? 0x0000FFFFu : 0u) |
                               ((kb0 + 1 <= kmax0) ? 0xFFFF0000u : 0u);
                unsigned mA2 = ((kb0 + 8 <= kmax0) ? 0x0000FFFFu : 0u) |
                               ((kb0 + 9 <= kmax0) ? 0xFFFF0000u : 0u);
                unsigned mB0 = ((kb0     <= kmax1) ? 0x0000FFFFu : 0u) |
                               ((kb0 + 1 <= kmax1) ? 0xFFFF0000u : 0u);
                unsigned mB2 = ((kb0 + 8 <= kmax1) ? 0x0000FFFFu : 0u) |
                               ((kb0 + 9 <= kmax1) ? 0xFFFF0000u : 0u);
                unsigned am0 = pa.x & mA0, am2 = pa.y & mA2;
                unsigned bm0 = pb.x & mB0, bm2 = pb.y & mB2;
                unsigned ax0 = pa.x & ~mA0, ax2 = pa.y & ~mA2;
                unsigned bx0 = pb.x & ~mB0, bx2 = pb.y & ~mB2;
#pragma unroll
                for (int nf = 0; nf < 8; nf++) {
                    int n = cc + nf * 8 + gid;
                    unsigned v0 = *(const unsigned*)(V2c + (ks * 8 + tig) * V2ST + n);
                    unsigned v1 = *(const unsigned*)(V2c + (ks * 8 + tig + 4) * V2ST + n);
                    mma16h(Om[nf], am0, bm0, am2, bm2, v0, v1);
                    mma16h(Ox[nf], ax0, bx0, ax2, bx2, v0, v1);
                }
            }
        }
    }

    // epilogue: atomic adds into zeroed Out
    float alpha = 1.f / (1.f + __expf(-__ldg(alpha_p)));
    float wp0 = alpha / sp0;
    float wp1 = alpha / sp1;
    float wu0 = (1.f - alpha) / (sp0 + sx0);
    float wu1 = (1.f - alpha) / (sp1 + sx1);

    int qg0 = Q0 + r0, qg1 = Q0 + r1;
    float* O0 = Out + ((size_t)b * T_ + qg0) * HD;
    float* O1 = Out + ((size_t)b * T_ + qg1) * HD;
    float* U0 = Out + ((size_t)b * T_ + (T_ - 1 - qg0)) * HD;
    float* U1 = Out + ((size_t)b * T_ + (T_ - 1 - qg1)) * HD;
#pragma unroll
    for (int nf = 0; nf < 8; nf++) {
        int col = cc + nf * 8 + 2 * tig;
        atomicAdd(O0 + col,     Om[nf][0] * wp0);
        atomicAdd(O0 + col + 1, Om[nf][1] * wp0);
        atomicAdd(O1 + col,     Om[nf][2] * wp1);
        atomicAdd(O1 + col + 1, Om[nf][3] * wp1);
        atomicAdd(U0 + col,     (Om[nf][0] + Ox[nf][0]) * wu0);
        atomicAdd(U0 + col + 1, (Om[nf][1] + Ox[nf][1]) * wu0);
        atomicAdd(U1 + col,     (Om[nf][2] + Ox[nf][2]) * wu1);
        atomicAdd(U1 + col + 1, (Om[nf][3] + Ox[nf][3]) * wu1);
    }
}

// ---------------- launch ----------------
extern "C" void kernel_launch(void* const* d_in, const int* in_sizes, int n_in,
                              void* d_out, int out_size) {
    const float* x  = (const float*)d_in[0];
    const float* Wq = (const float*)d_in[1];
    const float* Wk = (const float*)d_in[2];
    const float* Wv = (const float*)d_in[3];
    const float* fa = (const float*)d_in[9];
    float* out = (float*)d_out;

    const int PROJ_SMEM = (2 * ABUF + 2 * BBUF) * 4;    // 69632 B
    const int ATTN_SMEM = 768 * 4 + (128 * QSTh + 2 * 64 * QSTh + 128 * PSTh) * 2
                          + 2 * 32 * V2ST * 4;          // 132096 B
    cudaFuncSetAttribute(proj_k, cudaFuncAttributeMaxDynamicSharedMemorySize, PROJ_SMEM);
    cudaFuncSetAttribute(attn_k, cudaFuncAttributeMaxDynamicSharedMemorySize, ATTN_SMEM);

    theta_k<<<1, 64>>>();
    rope_table_k<<<T_, 64>>>();
    cvtW_k<<<192, 256>>>(Wq, Wk, Wv);
    pool_x_k<<<(B_ * TKP * 128) / 256, 256>>>(x);
    proj_k<<<192, 256, PROJ_SMEM>>>(x);
    ropeh_k<<<(B_ * T_ * 4) / 256, 256>>>(0);
    ropeh_k<<<(B_ * TKP * 4) / 256, 256>>>(1);
    vpack_k<<<(B_ * 512 * 8) / 256, 256>>>();
    zero_k<<<(B_ * T_ * HD / 4) / 256, 256>>>(out);
    attn_k<<<dim3(T_ / 128, B_), 512, ATTN_SMEM>>>(fa, out);
}